// round 13
// baseline (speedup 1.0000x reference)
#include <cuda_runtime.h>
#include <cuda_fp16.h>
#include <cstdint>
#include <math.h>

// ---------------- problem constants ----------------
#define L_X   1536
#define S_C   512
#define TT    2048          // L_X + S_C
#define D     1024
#define H     16
#define HD    64
#define FF    4096

// ---------------- scratch (device globals; no cudaMalloc allowed) ----------
__device__ float g_x1x[L_X * D];
__device__ float g_x1c[S_C * D];

// fp16 buffers
__device__ __half g_w16  [33554432];
__device__ __half g_qk16x[L_X * 2 * D];
__device__ __half g_qk16c[S_C * 2 * D];
__device__ __half g_cln16[S_C * D];
__device__ __half g_xln16[L_X * D];
__device__ __half g_q16  [H * TT * HD];
__device__ __half g_k16  [H * TT * HD];
__device__ __half g_v16t [H * HD * TT];
__device__ __half g_y16  [TT * D];
__device__ __half g_h16x [L_X * D];
__device__ __half g_h16c [S_C * D];
__device__ __half g_t16x1[L_X * FF];
__device__ __half g_t16c1[S_C * FF];
__device__ __half g_g16x [L_X * FF];
__device__ __half g_g16c [S_C * FF];

// arena offsets (halves)
#define O_PCQK 0
#define O_PXQK 2097152
#define O_PCV  4194304
#define O_PXV  5242880
#define O_P1P  6291456
#define O_P2P  7340032
#define O_P1W1 8388608
#define O_P1W3 12582912
#define O_P2W1 16777216
#define O_P2W3 20971520
#define O_P1W2 25165824
#define O_P2W2 29360128

// ---------------- utils ----------------
__device__ __forceinline__ float warpSum(float v) {
    #pragma unroll
    for (int o = 16; o > 0; o >>= 1) v += __shfl_xor_sync(0xffffffffu, v, o);
    return v;
}
__device__ __forceinline__ float ex2f(float x) {
    float y;
    asm("ex2.approx.f32 %0, %1;" : "=f"(y) : "f"(x));
    return y;
}
__device__ __forceinline__ void mma_f16(float* d, const uint32_t* a, const uint32_t* b) {
    asm volatile(
        "mma.sync.aligned.m16n8k16.row.col.f32.f16.f16.f32 "
        "{%0,%1,%2,%3}, {%4,%5,%6,%7}, {%8,%9}, {%0,%1,%2,%3};"
        : "+f"(d[0]), "+f"(d[1]), "+f"(d[2]), "+f"(d[3])
        : "r"(a[0]), "r"(a[1]), "r"(a[2]), "r"(a[3]), "r"(b[0]), "r"(b[1]));
}
__device__ __forceinline__ void ldsm_x4(uint32_t* r, uint32_t addr) {
    asm volatile("ldmatrix.sync.aligned.m8n8.x4.shared.b16 {%0,%1,%2,%3}, [%4];"
        : "=r"(r[0]), "=r"(r[1]), "=r"(r[2]), "=r"(r[3]) : "r"(addr));
}
__device__ __forceinline__ uint32_t smem_u32(const void* p) {
    uint32_t a;
    asm("{ .reg .u64 t; cvta.to.shared.u64 t, %1; cvt.u32.u64 %0, t; }" : "=r"(a) : "l"(p));
    return a;
}
__device__ __forceinline__ void cp_async16(uint32_t saddr, const void* gaddr) {
    asm volatile("cp.async.cg.shared.global [%0], [%1], 16;" :: "r"(saddr), "l"(gaddr));
}
#define CP_COMMIT() asm volatile("cp.async.commit_group;" ::: "memory")
#define CP_WAIT0()  asm volatile("cp.async.wait_group 0;" ::: "memory")
#define CP_WAIT1()  asm volatile("cp.async.wait_group 1;" ::: "memory")

// ---------------- weight fp32 -> fp16 conversion ----------------
struct WJob { const float* src; __half* dst; int off; };
struct WJobs { WJob j[12]; };

__global__ __launch_bounds__(256) void cvt16(WJobs J) {
    int ji = 0;
    #pragma unroll
    for (int t = 1; t < 12; t++) if ((int)blockIdx.x >= J.j[t].off) ji = t;
    size_t idx = ((size_t)(blockIdx.x - J.j[ji].off) * 256 + threadIdx.x) * 8;
    const float4* s = (const float4*)(J.j[ji].src + idx);
    float4 v0 = s[0], v1 = s[1];
    __half2* d = (__half2*)(J.j[ji].dst + idx);
    d[0] = __floats2half2_rn(v0.x, v0.y);
    d[1] = __floats2half2_rn(v0.z, v0.w);
    d[2] = __floats2half2_rn(v1.x, v1.y);
    d[3] = __floats2half2_rn(v1.z, v1.w);
}

// ---------------- LayerNorm pair -> fp16 (row cached in registers) -----
__global__ __launch_bounds__(256)
void ln2_kernel(const float* __restrict__ in0, __half* __restrict__ out0,
                int rows0,
                const float* __restrict__ in1, __half* __restrict__ out1) {
    int row = blockIdx.x;
    const float* x;
    __half* o;
    if (row < rows0) { x = in0 + (size_t)row * D; o = out0 + (size_t)row * D; }
    else             { x = in1 + (size_t)(row - rows0) * D; o = out1 + (size_t)(row - rows0) * D; }
    float4 v = *(const float4*)(x + threadIdx.x * 4);
    float s = v.x + v.y + v.z + v.w;
    float ss = v.x * v.x + v.y * v.y + v.z * v.z + v.w * v.w;
    __shared__ float shs[8], shss[8];
    float ws = warpSum(s), wss = warpSum(ss);
    int w = threadIdx.x >> 5;
    if ((threadIdx.x & 31) == 0) { shs[w] = ws; shss[w] = wss; }
    __syncthreads();
    float ts = 0.f, tss = 0.f;
    #pragma unroll
    for (int i = 0; i < 8; i++) { ts += shs[i]; tss += shss[i]; }
    float mean = ts * (1.0f / D);
    float var  = tss * (1.0f / D) - mean * mean;
    float inv  = rsqrtf(var + 1e-6f);
    __half2* o2 = (__half2*)(o + threadIdx.x * 4);
    o2[0] = __floats2half2_rn((v.x - mean) * inv, (v.y - mean) * inv);
    o2[1] = __floats2half2_rn((v.z - mean) * inv, (v.w - mean) * inv);
}

// ======================================================================
// Multi-job fp16 GEMM (m16n8k16), K-chunk 64, 3-stage cp.async, ldmatrix.
// mode 0: fp32 row-major (+resid). mode 1: fp16 V dim-major.
// mode 2: fp16 row-major. mode 3: fp16 gated (silu(gate)*acc), gate=resid.
// smem row: 64 halves + 8 pad = 72 halves (144 B) — conflict-free ldmatrix.
// ======================================================================
struct GJob {
    const __half* A; const __half* B; const float* bias; const float* resid;
    void* C; int N, K, off, mode, t_off;
};
struct GJobs { GJob j[4]; int n; };

#define HROW 144                         // bytes per smem row
#define OPBYTES (128 * HROW)             // 18432 bytes per operand per stage
#define STB (2 * OPBYTES)                // stage bytes
#define MMG_SMEM (3 * STB)               // 110592 bytes

__global__ __launch_bounds__(128)
void mma_gemm_mj(GJobs jobs) {
    int ji = 0;
    if (jobs.n > 1 && (int)blockIdx.x >= jobs.j[1].off) ji = 1;
    if (jobs.n > 2 && (int)blockIdx.x >= jobs.j[2].off) ji = 2;
    if (jobs.n > 3 && (int)blockIdx.x >= jobs.j[3].off) ji = 3;
    const __half* A = jobs.j[ji].A;
    const __half* B = jobs.j[ji].B;
    const float* bias = jobs.j[ji].bias;
    const float* resid = jobs.j[ji].resid;
    void* C = jobs.j[ji].C;
    int N = jobs.j[ji].N, K = jobs.j[ji].K;
    int mode = jobs.j[ji].mode, t_off = jobs.j[ji].t_off;
    int lid0 = blockIdx.x - jobs.j[ji].off;
    int nbx = N >> 7;
    int by = lid0 / nbx, bx = lid0 - by * nbx;
    int m0 = by * 128, n0 = bx * 128;

    extern __shared__ uint32_t smw[];
    uint32_t sbase = smem_u32(smw);
    int tid = threadIdx.x;
    int wid = tid >> 5, lane = tid & 31;
    int gid = lane >> 2, tig = lane & 3;
    int warp_m = wid >> 1, warp_n = wid & 1;

    float acc[4][8][4];
    #pragma unroll
    for (int mt = 0; mt < 4; mt++)
        #pragma unroll
        for (int nt = 0; nt < 8; nt++)
            #pragma unroll
            for (int e = 0; e < 4; e++) acc[mt][nt][e] = 0.f;

    const int nchunk = K >> 6;          // 64 halves per chunk
    int lrow = tid >> 3;                // 0..15
    int lblk = tid & 7;                 // 16B block within 128B row

    int tileid = lane >> 3;
    uint32_t aoff = (uint32_t)(warp_m * 64 + (tileid & 1) * 8 + (lane & 7)) * HROW
                    + (uint32_t)(tileid >> 1) * 16;
    uint32_t boff = (uint32_t)(warp_n * 64 + (tileid >> 1) * 8 + (lane & 7)) * HROW
                    + (uint32_t)(tileid & 1) * 16;

    #pragma unroll
    for (int pc = 0; pc < 2; pc++) {
        const __half* Ap = A + (size_t)m0 * K + pc * 64 + lblk * 8;
        const __half* Bp = B + (size_t)n0 * K + pc * 64 + lblk * 8;
        uint32_t sA = sbase + pc * STB;
        uint32_t sB = sA + OPBYTES;
        #pragma unroll
        for (int l = 0; l < 8; l++) {
            int r = lrow + l * 16;
            uint32_t so = r * HROW + lblk * 16;
            cp_async16(sA + so, Ap + (size_t)r * K);
            cp_async16(sB + so, Bp + (size_t)r * K);
        }
        CP_COMMIT();
    }

    int st = 0;
    for (int i = 0; i < nchunk; i++) {
        CP_WAIT1();
        __syncthreads();
        if (i + 2 < nchunk) {
            int ps = st + 2; if (ps >= 3) ps -= 3;
            const __half* Ap = A + (size_t)m0 * K + (i + 2) * 64 + lblk * 8;
            const __half* Bp = B + (size_t)n0 * K + (i + 2) * 64 + lblk * 8;
            uint32_t sA = sbase + ps * STB;
            uint32_t sB = sA + OPBYTES;
            #pragma unroll
            for (int l = 0; l < 8; l++) {
                int r = lrow + l * 16;
                uint32_t so = r * HROW + lblk * 16;
                cp_async16(sA + so, Ap + (size_t)r * K);
                cp_async16(sB + so, Bp + (size_t)r * K);
            }
        }
        CP_COMMIT();
        uint32_t stA = sbase + st * STB;
        uint32_t stB = stA + OPBYTES;
        #pragma unroll
        for (int s = 0; s < 4; s++) {
            uint32_t kbyte = s * 32;
            uint32_t af[4][4], bf[4][4];
            #pragma unroll
            for (int mt = 0; mt < 4; mt++)
                ldsm_x4(af[mt], stA + aoff + (uint32_t)mt * (16 * HROW) + kbyte);
            #pragma unroll
            for (int ntp = 0; ntp < 4; ntp++)
                ldsm_x4(bf[ntp], stB + boff + (uint32_t)ntp * (16 * HROW) + kbyte);
            #pragma unroll
            for (int mt = 0; mt < 4; mt++)
                #pragma unroll
                for (int ntp = 0; ntp < 4; ntp++) {
                    mma_f16(acc[mt][ntp * 2 + 0], af[mt], &bf[ntp][0]);
                    mma_f16(acc[mt][ntp * 2 + 1], af[mt], &bf[ntp][2]);
                }
        }
        st++; if (st >= 3) st = 0;
    }

    const float L2E = 1.4426950408889634f;
    #pragma unroll
    for (int mt = 0; mt < 4; mt++) {
        #pragma unroll
        for (int nt = 0; nt < 8; nt++) {
            int row = m0 + warp_m * 64 + mt * 16 + gid;
            int col = n0 + warp_n * 64 + nt * 8 + tig * 2;
            #pragma unroll
            for (int half = 0; half < 2; half++) {
                int r = row + half * 8;
                float2 v = make_float2(acc[mt][nt][half * 2], acc[mt][nt][half * 2 + 1]);
                if (bias) {
                    float2 bv2 = *(const float2*)(bias + col);
                    v.x += bv2.x; v.y += bv2.y;
                }
                if (mode == 0) {
                    float* Cf = (float*)C;
                    size_t off = (size_t)r * N + col;
                    if (resid) {
                        float2 rv = *(const float2*)(resid + off);
                        v.x += rv.x; v.y += rv.y;
                    }
                    *(float2*)(Cf + off) = v;
                } else if (mode == 1) {
                    __half* Ch = (__half*)C;
                    int hh = col >> 6, dd = col & 63;
                    Ch[((size_t)hh * HD + dd) * TT + t_off + r]     = __float2half_rn(v.x);
                    Ch[((size_t)hh * HD + dd + 1) * TT + t_off + r] = __float2half_rn(v.y);
                } else if (mode == 2) {
                    __half* Ch = (__half*)C;
                    *(__half2*)(Ch + (size_t)r * N + col) = __floats2half2_rn(v.x, v.y);
                } else {
                    // mode 3: gated w3: out = silu(t1) * (acc+bias)
                    const __half* gate = (const __half*)resid;
                    __half* Ch = (__half*)C;
                    size_t off = (size_t)r * N + col;
                    float2 t1v = __half22float2(*(const __half2*)(gate + off));
                    float s0 = t1v.x / (1.0f + ex2f(-t1v.x * L2E)) * v.x;
                    float s1 = t1v.y / (1.0f + ex2f(-t1v.y * L2E)) * v.y;
                    *(__half2*)(Ch + off) = __floats2half2_rn(s0, s1);
                }
            }
        }
    }
}

// ---------------- qk finish: warp per (t,h), lane owns RoPE pair --------
__global__ __launch_bounds__(256)
void qk_finish_all(const __half* __restrict__ qkc, const __half* __restrict__ qkx,
                   const float* __restrict__ cqn, const float* __restrict__ ckn,
                   const float* __restrict__ xqn, const float* __restrict__ xkn,
                   const float* __restrict__ freqs,
                   __half* __restrict__ Q, __half* __restrict__ Ko) {
    int gidx = blockIdx.x * 8 + (threadIdx.x >> 5);
    int lane = threadIdx.x & 31;
    int t = gidx >> 4;
    int h = gidx & 15;
    const __half* qk; const float* qn; const float* kn; int row;
    if (t < S_C) { qk = qkc; qn = cqn; kn = ckn; row = t; }
    else         { qk = qkx; qn = xqn; kn = xkn; row = t - S_C; }
    size_t base = (size_t)row * (2 * D) + h * HD + lane * 2;
    float2 qv = __half22float2(*(const __half2*)(qk + base));
    float2 kv = __half22float2(*(const __half2*)(qk + base + D));
    float sq = qv.x * qv.x + qv.y * qv.y;
    float sk = kv.x * kv.x + kv.y * kv.y;
    #pragma unroll
    for (int o = 16; o > 0; o >>= 1) {
        sq += __shfl_xor_sync(0xffffffffu, sq, o);
        sk += __shfl_xor_sync(0xffffffffu, sk, o);
    }
    float rq = rsqrtf(sq * (1.0f / HD) + 1e-6f);
    float rk = rsqrtf(sk * (1.0f / HD) + 1e-6f);
    float2 qw = *(const float2*)(qn + lane * 2);
    float2 kw = *(const float2*)(kn + lane * 2);
    float q0 = qv.x * rq * qw.x, q1 = qv.y * rq * qw.y;
    float k0 = kv.x * rk * kw.x, k1 = kv.y * rk * kw.y;
    float2 f = *(const float2*)(freqs + ((size_t)t * 32 + lane) * 2);
    float cs = f.x, sn = f.y;
    const float QSC = 0.125f * 1.4426950408889634f;
    float oq0 = (q0 * cs - q1 * sn) * QSC;
    float oq1 = (q0 * sn + q1 * cs) * QSC;
    float ok0 = k0 * cs - k1 * sn;
    float ok1 = k0 * sn + k1 * cs;
    size_t off = ((size_t)h * TT + t) * HD + lane * 2;
    *(__half2*)(Q + off)  = __floats2half2_rn(oq0, oq1);
    *(__half2*)(Ko + off) = __floats2half2_rn(ok0, ok1);
}

// ======================================================================
// fp16 tensor-core flash attention, ldmatrix fragments (unchanged R12).
// ======================================================================
#define AHS 72
#define AWS 36
#define ATN_SMEM (6 * 64 * AHS * 2)

__global__ __launch_bounds__(128)
void attn_tc(const __half* __restrict__ Q, const __half* __restrict__ K,
             const __half* __restrict__ V, __half* __restrict__ Y) {
    extern __shared__ uint32_t smw[];
    uint32_t sbase = smem_u32(smw);
    int tid = threadIdx.x, wid = tid >> 5, lane = tid & 31;
    int gid = lane >> 2, tig = lane & 3;
    int bxr = 31 - blockIdx.x;
    int h = blockIdx.y;
    int q0 = bxr * 64;
    const __half* Qh = Q + (size_t)h * TT * HD;
    const __half* Kh = K + (size_t)h * TT * HD;
    const __half* Vh = V + (size_t)h * HD * TT;

    const uint32_t* QsW = smw;
    uint32_t* PwW = smw + 5 * 64 * AWS;

    int lrow = tid >> 1;
    int lblk = tid & 1;

    int tileid = lane >> 3;
    uint32_t poff = (uint32_t)(wid * 16 + (tileid & 1) * 8 + (lane & 7)) * (AHS * 2)
                    + (uint32_t)(tileid >> 1) * 16;
    uint32_t boff = (uint32_t)((tileid >> 1) * 8 + (lane & 7)) * (AHS * 2)
                    + (uint32_t)(tileid & 1) * 16;

    {
        uint32_t qb = sbase;
        uint32_t kb = sbase + (1 * 64 * AWS) * 4;
        uint32_t vb = sbase + (3 * 64 * AWS) * 4;
        #pragma unroll
        for (int j = 0; j < 4; j++) {
            uint32_t so = (lrow * AHS + lblk * 32 + j * 8) * 2;
            cp_async16(qb + so, Qh + (size_t)(q0 + lrow) * HD + lblk * 32 + j * 8);
            cp_async16(kb + so, Kh + (size_t)lrow * HD + lblk * 32 + j * 8);
            cp_async16(vb + so, Vh + (size_t)lrow * TT + lblk * 32 + j * 8);
        }
        CP_COMMIT();
    }
    CP_WAIT0();
    __syncthreads();

    uint32_t qf[4][4];
    int qrow = wid * 16 + gid;
    #pragma unroll
    for (int ks = 0; ks < 4; ks++) {
        qf[ks][0] = QsW[qrow * AWS + ks * 8 + tig];
        qf[ks][1] = QsW[(qrow + 8) * AWS + ks * 8 + tig];
        qf[ks][2] = QsW[qrow * AWS + ks * 8 + tig + 4];
        qf[ks][3] = QsW[(qrow + 8) * AWS + ks * 8 + tig + 4];
    }
    __syncwarp();

    float ofr[8][4];
    #pragma unroll
    for (int ot = 0; ot < 8; ot++)
        #pragma unroll
        for (int e = 0; e < 4; e++) ofr[ot][e] = 0.f;
    float m0r = -INFINITY, m1r = -INFINITY, l0r = 0.f, l1r = 0.f;

    int ntile = bxr + 1;
    for (int kt = 0; kt < ntile; kt++) {
        int k0g = kt * 64;
        int buf = kt & 1;
        uint32_t kbase = sbase + ((1 + buf) * 64 * AWS) * 4;
        uint32_t vbase = sbase + ((3 + buf) * 64 * AWS) * 4;
        uint32_t pbase = sbase + (5 * 64 * AWS) * 4;
        if (kt > 0) { CP_WAIT0(); __syncthreads(); }
        float sacc[8][4];
        #pragma unroll
        for (int nt = 0; nt < 8; nt++)
            #pragma unroll
            for (int e = 0; e < 4; e++) sacc[nt][e] = 0.f;
        #pragma unroll
        for (int ks = 0; ks < 4; ks++) {
            uint32_t bk[4][4];
            #pragma unroll
            for (int kp = 0; kp < 4; kp++)
                ldsm_x4(bk[kp], kbase + boff + (uint32_t)kp * (16 * AHS * 2) + ks * 32);
            #pragma unroll
            for (int kp = 0; kp < 4; kp++) {
                mma_f16(sacc[kp * 2 + 0], qf[ks], &bk[kp][0]);
                mma_f16(sacc[kp * 2 + 1], qf[ks], &bk[kp][2]);
            }
        }
        if (kt + 1 < ntile) {
            uint32_t kb = sbase + ((1 + (buf ^ 1)) * 64 * AWS) * 4;
            uint32_t vb = sbase + ((3 + (buf ^ 1)) * 64 * AWS) * 4;
            const __half* Kp = Kh + (size_t)(k0g + 64) * HD;
            const __half* Vp = Vh + k0g + 64;
            #pragma unroll
            for (int j = 0; j < 4; j++) {
                uint32_t so = (lrow * AHS + lblk * 32 + j * 8) * 2;
                cp_async16(kb + so, Kp + (size_t)lrow * HD + lblk * 32 + j * 8);
                cp_async16(vb + so, Vp + (size_t)lrow * TT + lblk * 32 + j * 8);
            }
        }
        CP_COMMIT();
        if (kt == ntile - 1) {
            int r0 = q0 + wid * 16 + gid;
            #pragma unroll
            for (int nt = 0; nt < 8; nt++) {
                int c0 = k0g + nt * 8 + tig * 2;
                if (c0 > r0)     sacc[nt][0] = -INFINITY;
                if (c0 + 1 > r0) sacc[nt][1] = -INFINITY;
                if (c0 > r0 + 8)     sacc[nt][2] = -INFINITY;
                if (c0 + 1 > r0 + 8) sacc[nt][3] = -INFINITY;
            }
        }
        float tm0 = -INFINITY, tm1 = -INFINITY;
        #pragma unroll
        for (int nt = 0; nt < 8; nt++) {
            tm0 = fmaxf(tm0, fmaxf(sacc[nt][0], sacc[nt][1]));
            tm1 = fmaxf(tm1, fmaxf(sacc[nt][2], sacc[nt][3]));
        }
        #pragma unroll
        for (int o = 1; o < 4; o <<= 1) {
            tm0 = fmaxf(tm0, __shfl_xor_sync(0xffffffffu, tm0, o));
            tm1 = fmaxf(tm1, __shfl_xor_sync(0xffffffffu, tm1, o));
        }
        float nm0 = fmaxf(m0r, tm0), nm1 = fmaxf(m1r, tm1);
        float c0 = ex2f(m0r - nm0), c1 = ex2f(m1r - nm1);
        m0r = nm0; m1r = nm1;
        float ps0 = 0.f, ps1 = 0.f;
        int row0 = wid * 16 + gid, row1 = row0 + 8;
        #pragma unroll
        for (int nt = 0; nt < 8; nt++) {
            float p00 = ex2f(sacc[nt][0] - nm0);
            float p01 = ex2f(sacc[nt][1] - nm0);
            float p10 = ex2f(sacc[nt][2] - nm1);
            float p11 = ex2f(sacc[nt][3] - nm1);
            ps0 += p00 + p01; ps1 += p10 + p11;
            __half2 h0 = __floats2half2_rn(p00, p01);
            __half2 h1 = __floats2half2_rn(p10, p11);
            PwW[row0 * AWS + nt * 4 + tig] = *(uint32_t*)&h0;
            PwW[row1 * AWS + nt * 4 + tig] = *(uint32_t*)&h1;
        }
        #pragma unroll
        for (int o = 1; o < 4; o <<= 1) {
            ps0 += __shfl_xor_sync(0xffffffffu, ps0, o);
            ps1 += __shfl_xor_sync(0xffffffffu, ps1, o);
        }
        l0r = l0r * c0 + ps0;
        l1r = l1r * c1 + ps1;
        #pragma unroll
        for (int ot = 0; ot < 8; ot++) {
            ofr[ot][0] *= c0; ofr[ot][1] *= c0;
            ofr[ot][2] *= c1; ofr[ot][3] *= c1;
        }
        __syncwarp();
        #pragma unroll
        for (int ks = 0; ks < 4; ks++) {
            uint32_t af[4];
            ldsm_x4(af, pbase + poff + ks * 32);
            uint32_t bv[4][4];
            #pragma unroll
            for (int vp = 0; vp < 4; vp++)
                ldsm_x4(bv[vp], vbase + boff + (uint32_t)vp * (16 * AHS * 2) + ks * 32);
            #pragma unroll
            for (int vp = 0; vp < 4; vp++) {
                mma_f16(ofr[vp * 2 + 0], af, &bv[vp][0]);
                mma_f16(ofr[vp * 2 + 1], af, &bv[vp][2]);
            }
        }
        __syncwarp();
    }
    float i0 = 1.0f / l0r, i1 = 1.0f / l1r;
    int t0 = q0 + wid * 16 + gid, t1 = t0 + 8;
    #pragma unroll
    for (int ot = 0; ot < 8; ot++) {
        int col = h * HD + ot * 8 + tig * 2;
        *(__half2*)(Y + (size_t)t0 * D + col) = __floats2half2_rn(ofr[ot][0] * i0, ofr[ot][1] * i0);
        *(__half2*)(Y + (size_t)t1 * D + col) = __floats2half2_rn(ofr[ot][2] * i1, ofr[ot][3] * i1);
    }
}

// ---------------- host launcher ----------------
static inline int nct(int M, int N) { return (M / 128) * (N / 128); }

extern "C" void kernel_launch(void* const* d_in, const int* in_sizes, int n_in,
                              void* d_out, int out_size) {
    const float* x        = (const float*)d_in[0];
    const float* c        = (const float*)d_in[1];
    const float* freqs    = (const float*)d_in[2];
    const float* px_qk_w  = (const float*)d_in[3];
    const float* px_qn    = (const float*)d_in[4];
    const float* px_kn    = (const float*)d_in[5];
    const float* px_v_w   = (const float*)d_in[6];
    const float* px_v_b   = (const float*)d_in[7];
    const float* pc_qk_w  = (const float*)d_in[8];
    const float* pc_qn    = (const float*)d_in[9];
    const float* pc_kn    = (const float*)d_in[10];
    const float* pc_v_w   = (const float*)d_in[11];
    const float* pc_v_b   = (const float*)d_in[12];
    const float* p1_proj_w = (const float*)d_in[13];
    const float* p1_proj_b = (const float*)d_in[14];
    const float* p1_w1    = (const float*)d_in[15];
    const float* p1_b1    = (const float*)d_in[16];
    const float* p1_w3    = (const float*)d_in[17];
    const float* p1_b3    = (const float*)d_in[18];
    const float* p1_w2    = (const float*)d_in[19];
    const float* p1_b2    = (const float*)d_in[20];
    const float* p2_proj_w = (const float*)d_in[21];
    const float* p2_proj_b = (const float*)d_in[22];
    const float* p2_w1    = (const float*)d_in[23];
    const float* p2_b1    = (const float*)d_in[24];
    const float* p2_w3    = (const float*)d_in[25];
    const float* p2_b3    = (const float*)d_in[26];
    const float* p2_w2    = (const float*)d_in[27];
    const float* p2_b2    = (const float*)d_in[28];
    float* out = (float*)d_out;

    float *x1x, *x1c;
    __half *w16, *qk16x, *qk16c, *cln16, *xln16, *q16, *k16, *v16t, *y16;
    __half *h16x, *h16c, *t16x1, *t16c1, *g16x, *g16c;
    cudaGetSymbolAddress((void**)&x1x, g_x1x);
    cudaGetSymbolAddress((void**)&x1c, g_x1c);
    cudaGetSymbolAddress((void**)&w16,   g_w16);
    cudaGetSymbolAddress((void**)&qk16x, g_qk16x);
    cudaGetSymbolAddress((void**)&qk16c, g_qk16c);
    cudaGetSymbolAddress((void**)&cln16, g_cln16);
    cudaGetSymbolAddress((void**)&xln16, g_xln16);
    cudaGetSymbolAddress((void**)&q16,   g_q16);
    cudaGetSymbolAddress((void**)&k16,   g_k16);
    cudaGetSymbolAddress((void**)&v16t,  g_v16t);
    cudaGetSymbolAddress((void**)&y16,   g_y16);
    cudaGetSymbolAddress((void**)&h16x,  g_h16x);
    cudaGetSymbolAddress((void**)&h16c,  g_h16c);
    cudaGetSymbolAddress((void**)&t16x1, g_t16x1);
    cudaGetSymbolAddress((void**)&t16c1, g_t16c1);
    cudaGetSymbolAddress((void**)&g16x,  g_g16x);
    cudaGetSymbolAddress((void**)&g16c,  g_g16c);

    cudaFuncSetAttribute(attn_tc, cudaFuncAttributeMaxDynamicSharedMemorySize, ATN_SMEM);
    cudaFuncSetAttribute(mma_gemm_mj, cudaFuncAttributeMaxDynamicSharedMemorySize, MMG_SMEM);

    // 0) convert weights to fp16 arena
    {
        WJobs W;
        int o = 0;
        W.j[0]  = {pc_qk_w,  w16 + O_PCQK, o}; o += 1024;
        W.j[1]  = {px_qk_w,  w16 + O_PXQK, o}; o += 1024;
        W.j[2]  = {pc_v_w,   w16 + O_PCV,  o}; o += 512;
        W.j[3]  = {px_v_w,   w16 + O_PXV,  o}; o += 512;
        W.j[4]  = {p1_proj_w, w16 + O_P1P, o}; o += 512;
        W.j[5]  = {p2_proj_w, w16 + O_P2P, o}; o += 512;
        W.j[6]  = {p1_w1,    w16 + O_P1W1, o}; o += 2048;
        W.j[7]  = {p1_w3,    w16 + O_P1W3, o}; o += 2048;
        W.j[8]  = {p2_w1,    w16 + O_P2W1, o}; o += 2048;
        W.j[9]  = {p2_w3,    w16 + O_P2W3, o}; o += 2048;
        W.j[10] = {p1_w2,    w16 + O_P1W2, o}; o += 2048;
        W.j[11] = {p2_w2,    w16 + O_P2W2, o}; o += 2048;
        cvt16<<<o, 256>>>(W);
    }

    // 1) LayerNorm both streams -> fp16
    ln2_kernel<<<L_X + S_C, 256>>>(x, xln16, L_X, c, cln16);

    // 2) QKV GEMMs; qk fp16 out, V fp16 dim-major
    {
        GJobs J; J.n = 4;
        int o = 0;
        J.j[0] = {cln16, w16 + O_PCQK, nullptr, nullptr, qk16c, 2 * D, D, o, 2, 0};  o += nct(S_C, 2 * D);
        J.j[1] = {cln16, w16 + O_PCV,  pc_v_b,  nullptr, v16t,  D,     D, o, 1, 0};  o += nct(S_C, D);
        J.j[2] = {xln16, w16 + O_PXQK, nullptr, nullptr, qk16x, 2 * D, D, o, 2, 0};  o += nct(L_X, 2 * D);
        J.j[3] = {xln16, w16 + O_PXV,  px_v_b,  nullptr, v16t,  D,     D, o, 1, S_C}; o += nct(L_X, D);
        mma_gemm_mj<<<o, 128, MMG_SMEM>>>(J);
    }
    qk_finish_all<<<TT * H / 8, 256>>>(qk16c, qk16x, pc_qn, pc_kn, px_qn, px_kn, freqs, q16, k16);

    // 3) causal attention -> y fp16
    attn_tc<<<dim3(32, H), 128, ATN_SMEM>>>(q16, k16, v16t, y16);

    // 4) output projections (batched)
    const __half* yx16 = y16 + (size_t)S_C * D;
    {
        GJobs J; J.n = 2;
        int o = 0;
        J.j[0] = {yx16, w16 + O_P1P, p1_proj_b, x, x1x, D, D, o, 0, 0}; o += nct(L_X, D);
        J.j[1] = {y16,  w16 + O_P2P, p2_proj_b, c, x1c, D, D, o, 0, 0}; o += nct(S_C, D);
        J.j[2] = J.j[0]; J.j[3] = J.j[0];
        mma_gemm_mj<<<o, 128, MMG_SMEM>>>(J);
    }
    ln2_kernel<<<L_X + S_C, 256>>>(x1x, h16x, L_X, x1c, h16c);

    // 5a) w1 (batched) -> t1 fp16
    {
        GJobs J; J.n = 2;
        int o = 0;
        J.j[0] = {h16x, w16 + O_P1W1, p1_b1, nullptr, t16x1, FF, D, o, 2, 0}; o += nct(L_X, FF);
        J.j[1] = {h16c, w16 + O_P2W1, p2_b1, nullptr, t16c1, FF, D, o, 2, 0}; o += nct(S_C, FF);
        J.j[2] = J.j[0]; J.j[3] = J.j[0];
        mma_gemm_mj<<<o, 128, MMG_SMEM>>>(J);
    }
    // 5b) w3 with fused SiLU gate -> g fp16
    {
        GJobs J; J.n = 2;
        int o = 0;
        J.j[0] = {h16x, w16 + O_P1W3, p1_b3, (const float*)t16x1, g16x, FF, D, o, 3, 0}; o += nct(L_X, FF);
        J.j[1] = {h16c, w16 + O_P2W3, p2_b3, (const float*)t16c1, g16c, FF, D, o, 3, 0}; o += nct(S_C, FF);
        J.j[2] = J.j[0]; J.j[3] = J.j[0];
        mma_gemm_mj<<<o, 128, MMG_SMEM>>>(J);
    }

    // 6) w2 (batched)
    {
        GJobs J; J.n = 2;
        int o = 0;
        J.j[0] = {g16x, w16 + O_P1W2, p1_b2, x1x, out,                   D, FF, o, 0, 0}; o += nct(L_X, D);
        J.j[1] = {g16c, w16 + O_P2W2, p2_b2, x1c, out + (size_t)L_X * D, D, FF, o, 0, 0}; o += nct(S_C, D);
        J.j[2] = J.j[0]; J.j[3] = J.j[0];
        mma_gemm_mj<<<o, 128, MMG_SMEM>>>(J);
    }
}

// round 14
// speedup vs baseline: 1.0723x; 1.0723x over previous
#include <cuda_runtime.h>
#include <cuda_fp16.h>
#include <cstdint>
#include <math.h>

// ---------------- problem constants ----------------
#define L_X   1536
#define S_C   512
#define TT    2048          // L_X + S_C
#define D     1024
#define H     16
#define HD    64
#define FF    4096

// ---------------- scratch (device globals; no cudaMalloc allowed) ----------
__device__ float g_x1x[L_X * D];
__device__ float g_x1c[S_C * D];

// fp16 buffers
__device__ __half g_w16  [33554432];
__device__ __half g_qk16x[L_X * 2 * D];
__device__ __half g_qk16c[S_C * 2 * D];
__device__ __half g_cln16[S_C * D];
__device__ __half g_xln16[L_X * D];
__device__ __half g_q16  [H * TT * HD];
__device__ __half g_k16  [H * TT * HD];
__device__ __half g_v16t [H * HD * TT];
__device__ __half g_y16  [TT * D];
__device__ __half g_h16x [L_X * D];
__device__ __half g_h16c [S_C * D];
__device__ __half g_t16x1[L_X * FF];
__device__ __half g_t16c1[S_C * FF];
__device__ __half g_g16x [L_X * FF];
__device__ __half g_g16c [S_C * FF];

// arena offsets (halves)
#define O_PCQK 0
#define O_PXQK 2097152
#define O_PCV  4194304
#define O_PXV  5242880
#define O_P1P  6291456
#define O_P2P  7340032
#define O_P1W1 8388608
#define O_P1W3 12582912
#define O_P2W1 16777216
#define O_P2W3 20971520
#define O_P1W2 25165824
#define O_P2W2 29360128

// ---------------- utils ----------------
__device__ __forceinline__ float warpSum(float v) {
    #pragma unroll
    for (int o = 16; o > 0; o >>= 1) v += __shfl_xor_sync(0xffffffffu, v, o);
    return v;
}
__device__ __forceinline__ float ex2f(float x) {
    float y;
    asm("ex2.approx.f32 %0, %1;" : "=f"(y) : "f"(x));
    return y;
}
__device__ __forceinline__ void mma_f16(float* d, const uint32_t* a, const uint32_t* b) {
    asm volatile(
        "mma.sync.aligned.m16n8k16.row.col.f32.f16.f16.f32 "
        "{%0,%1,%2,%3}, {%4,%5,%6,%7}, {%8,%9}, {%0,%1,%2,%3};"
        : "+f"(d[0]), "+f"(d[1]), "+f"(d[2]), "+f"(d[3])
        : "r"(a[0]), "r"(a[1]), "r"(a[2]), "r"(a[3]), "r"(b[0]), "r"(b[1]));
}
__device__ __forceinline__ void ldsm_x4(uint32_t* r, uint32_t addr) {
    asm volatile("ldmatrix.sync.aligned.m8n8.x4.shared.b16 {%0,%1,%2,%3}, [%4];"
        : "=r"(r[0]), "=r"(r[1]), "=r"(r[2]), "=r"(r[3]) : "r"(addr));
}
__device__ __forceinline__ uint32_t smem_u32(const void* p) {
    uint32_t a;
    asm("{ .reg .u64 t; cvta.to.shared.u64 t, %1; cvt.u32.u64 %0, t; }" : "=r"(a) : "l"(p));
    return a;
}
__device__ __forceinline__ void cp_async16(uint32_t saddr, const void* gaddr) {
    asm volatile("cp.async.cg.shared.global [%0], [%1], 16;" :: "r"(saddr), "l"(gaddr));
}
#define CP_COMMIT() asm volatile("cp.async.commit_group;" ::: "memory")
#define CP_WAIT0()  asm volatile("cp.async.wait_group 0;" ::: "memory")
#define CP_WAIT1()  asm volatile("cp.async.wait_group 1;" ::: "memory")

// ---------------- weight fp32 -> fp16 conversion ----------------
struct WJob { const float* src; __half* dst; int off; };
struct WJobs { WJob j[12]; };

__global__ __launch_bounds__(256) void cvt16(WJobs J) {
    int ji = 0;
    #pragma unroll
    for (int t = 1; t < 12; t++) if ((int)blockIdx.x >= J.j[t].off) ji = t;
    size_t idx = ((size_t)(blockIdx.x - J.j[ji].off) * 256 + threadIdx.x) * 8;
    const float4* s = (const float4*)(J.j[ji].src + idx);
    float4 v0 = s[0], v1 = s[1];
    __half2* d = (__half2*)(J.j[ji].dst + idx);
    d[0] = __floats2half2_rn(v0.x, v0.y);
    d[1] = __floats2half2_rn(v0.z, v0.w);
    d[2] = __floats2half2_rn(v1.x, v1.y);
    d[3] = __floats2half2_rn(v1.z, v1.w);
}

// ---------------- LayerNorm pair -> fp16 (row cached in registers) -----
__global__ __launch_bounds__(256)
void ln2_kernel(const float* __restrict__ in0, __half* __restrict__ out0,
                int rows0,
                const float* __restrict__ in1, __half* __restrict__ out1) {
    int row = blockIdx.x;
    const float* x;
    __half* o;
    if (row < rows0) { x = in0 + (size_t)row * D; o = out0 + (size_t)row * D; }
    else             { x = in1 + (size_t)(row - rows0) * D; o = out1 + (size_t)(row - rows0) * D; }
    float4 v = *(const float4*)(x + threadIdx.x * 4);
    float s = v.x + v.y + v.z + v.w;
    float ss = v.x * v.x + v.y * v.y + v.z * v.z + v.w * v.w;
    __shared__ float shs[8], shss[8];
    float ws = warpSum(s), wss = warpSum(ss);
    int w = threadIdx.x >> 5;
    if ((threadIdx.x & 31) == 0) { shs[w] = ws; shss[w] = wss; }
    __syncthreads();
    float ts = 0.f, tss = 0.f;
    #pragma unroll
    for (int i = 0; i < 8; i++) { ts += shs[i]; tss += shss[i]; }
    float mean = ts * (1.0f / D);
    float var  = tss * (1.0f / D) - mean * mean;
    float inv  = rsqrtf(var + 1e-6f);
    __half2* o2 = (__half2*)(o + threadIdx.x * 4);
    o2[0] = __floats2half2_rn((v.x - mean) * inv, (v.y - mean) * inv);
    o2[1] = __floats2half2_rn((v.z - mean) * inv, (v.w - mean) * inv);
}

// ======================================================================
// Multi-job fp16 GEMM (m16n8k16), K-chunk 32, 3-stage cp.async, ldmatrix.
// (R12 configuration: 61.4KB smem -> 3 CTAs/SM.)
// mode 0: fp32 row-major (+resid). mode 1: fp16 V dim-major.
// mode 2: fp16 row-major. mode 3: fp16 gated (silu(gate)*acc), gate=resid.
// ======================================================================
struct GJob {
    const __half* A; const __half* B; const float* bias; const float* resid;
    void* C; int N, K, off, mode, t_off;
};
struct GJobs { GJob j[4]; int n; };

#define HST 20
#define HBUF (128 * HST)
#define MMG_SMEM (3 * 2 * HBUF * 4)

__global__ __launch_bounds__(128)
void mma_gemm_mj(GJobs jobs) {
    int ji = 0;
    if (jobs.n > 1 && (int)blockIdx.x >= jobs.j[1].off) ji = 1;
    if (jobs.n > 2 && (int)blockIdx.x >= jobs.j[2].off) ji = 2;
    if (jobs.n > 3 && (int)blockIdx.x >= jobs.j[3].off) ji = 3;
    const __half* A = jobs.j[ji].A;
    const __half* B = jobs.j[ji].B;
    const float* bias = jobs.j[ji].bias;
    const float* resid = jobs.j[ji].resid;
    void* C = jobs.j[ji].C;
    int N = jobs.j[ji].N, K = jobs.j[ji].K;
    int mode = jobs.j[ji].mode, t_off = jobs.j[ji].t_off;
    int lid0 = blockIdx.x - jobs.j[ji].off;
    int nbx = N >> 7;
    int by = lid0 / nbx, bx = lid0 - by * nbx;
    int m0 = by * 128, n0 = bx * 128;

    extern __shared__ uint32_t smw[];
    uint32_t sbase = smem_u32(smw);
    int tid = threadIdx.x;
    int wid = tid >> 5, lane = tid & 31;
    int gid = lane >> 2, tig = lane & 3;
    int warp_m = wid >> 1, warp_n = wid & 1;

    float acc[4][8][4];
    #pragma unroll
    for (int mt = 0; mt < 4; mt++)
        #pragma unroll
        for (int nt = 0; nt < 8; nt++)
            #pragma unroll
            for (int e = 0; e < 4; e++) acc[mt][nt][e] = 0.f;

    const int nchunk = K >> 5;
    int lrow = tid >> 2;
    int lblk = tid & 3;

    int tileid = lane >> 3;
    uint32_t aoff = (uint32_t)(warp_m * 64 + (tileid & 1) * 8 + (lane & 7)) * 80
                    + (uint32_t)(tileid >> 1) * 16;
    uint32_t boff = (uint32_t)(warp_n * 64 + (tileid >> 1) * 8 + (lane & 7)) * 80
                    + (uint32_t)(tileid & 1) * 16;

    #pragma unroll
    for (int pc = 0; pc < 2; pc++) {
        const __half* Ap = A + (size_t)m0 * K + pc * 32 + lblk * 8;
        const __half* Bp = B + (size_t)n0 * K + pc * 32 + lblk * 8;
        uint32_t sA = sbase + pc * 2 * HBUF * 4;
        uint32_t sB = sA + HBUF * 4;
        #pragma unroll
        for (int l = 0; l < 4; l++) {
            int r = lrow + l * 32;
            uint32_t so = (r * HST + lblk * 4) * 4;
            cp_async16(sA + so, Ap + (size_t)r * K);
            cp_async16(sB + so, Bp + (size_t)r * K);
        }
        CP_COMMIT();
    }

    int st = 0;
    for (int i = 0; i < nchunk; i++) {
        CP_WAIT1();
        __syncthreads();
        if (i + 2 < nchunk) {
            int ps = st + 2; if (ps >= 3) ps -= 3;
            const __half* Ap = A + (size_t)m0 * K + (i + 2) * 32 + lblk * 8;
            const __half* Bp = B + (size_t)n0 * K + (i + 2) * 32 + lblk * 8;
            uint32_t sA = sbase + ps * 2 * HBUF * 4;
            uint32_t sB = sA + HBUF * 4;
            #pragma unroll
            for (int l = 0; l < 4; l++) {
                int r = lrow + l * 32;
                uint32_t so = (r * HST + lblk * 4) * 4;
                cp_async16(sA + so, Ap + (size_t)r * K);
                cp_async16(sB + so, Bp + (size_t)r * K);
            }
        }
        CP_COMMIT();
        uint32_t stA = sbase + st * 2 * HBUF * 4;
        uint32_t stB = stA + HBUF * 4;
        #pragma unroll
        for (int s = 0; s < 2; s++) {
            uint32_t kbyte = s * 32;
            uint32_t af[4][4], bf[4][4];
            #pragma unroll
            for (int mt = 0; mt < 4; mt++)
                ldsm_x4(af[mt], stA + aoff + (uint32_t)mt * (16 * 80) + kbyte);
            #pragma unroll
            for (int ntp = 0; ntp < 4; ntp++)
                ldsm_x4(bf[ntp], stB + boff + (uint32_t)ntp * (16 * 80) + kbyte);
            #pragma unroll
            for (int mt = 0; mt < 4; mt++)
                #pragma unroll
                for (int ntp = 0; ntp < 4; ntp++) {
                    mma_f16(acc[mt][ntp * 2 + 0], af[mt], &bf[ntp][0]);
                    mma_f16(acc[mt][ntp * 2 + 1], af[mt], &bf[ntp][2]);
                }
        }
        st++; if (st >= 3) st = 0;
    }

    const float L2E = 1.4426950408889634f;
    #pragma unroll
    for (int mt = 0; mt < 4; mt++) {
        #pragma unroll
        for (int nt = 0; nt < 8; nt++) {
            int row = m0 + warp_m * 64 + mt * 16 + gid;
            int col = n0 + warp_n * 64 + nt * 8 + tig * 2;
            #pragma unroll
            for (int half = 0; half < 2; half++) {
                int r = row + half * 8;
                float2 v = make_float2(acc[mt][nt][half * 2], acc[mt][nt][half * 2 + 1]);
                if (bias) {
                    float2 bv2 = *(const float2*)(bias + col);
                    v.x += bv2.x; v.y += bv2.y;
                }
                if (mode == 0) {
                    float* Cf = (float*)C;
                    size_t off = (size_t)r * N + col;
                    if (resid) {
                        float2 rv = *(const float2*)(resid + off);
                        v.x += rv.x; v.y += rv.y;
                    }
                    *(float2*)(Cf + off) = v;
                } else if (mode == 1) {
                    __half* Ch = (__half*)C;
                    int hh = col >> 6, dd = col & 63;
                    Ch[((size_t)hh * HD + dd) * TT + t_off + r]     = __float2half_rn(v.x);
                    Ch[((size_t)hh * HD + dd + 1) * TT + t_off + r] = __float2half_rn(v.y);
                } else if (mode == 2) {
                    __half* Ch = (__half*)C;
                    *(__half2*)(Ch + (size_t)r * N + col) = __floats2half2_rn(v.x, v.y);
                } else {
                    // mode 3: out = silu(t1) * (acc + bias); gate (t1) passed via resid
                    const __half* gate = (const __half*)resid;
                    __half* Ch = (__half*)C;
                    size_t off = (size_t)r * N + col;
                    float2 t1v = __half22float2(*(const __half2*)(gate + off));
                    float s0 = t1v.x / (1.0f + ex2f(-t1v.x * L2E)) * v.x;
                    float s1 = t1v.y / (1.0f + ex2f(-t1v.y * L2E)) * v.y;
                    *(__half2*)(Ch + off) = __floats2half2_rn(s0, s1);
                }
            }
        }
    }
}

// ---------------- qk finish: warp per (t,h), lane owns RoPE pair --------
__global__ __launch_bounds__(256)
void qk_finish_all(const __half* __restrict__ qkc, const __half* __restrict__ qkx,
                   const float* __restrict__ cqn, const float* __restrict__ ckn,
                   const float* __restrict__ xqn, const float* __restrict__ xkn,
                   const float* __restrict__ freqs,
                   __half* __restrict__ Q, __half* __restrict__ Ko) {
    int gidx = blockIdx.x * 8 + (threadIdx.x >> 5);
    int lane = threadIdx.x & 31;
    int t = gidx >> 4;
    int h = gidx & 15;
    const __half* qk; const float* qn; const float* kn; int row;
    if (t < S_C) { qk = qkc; qn = cqn; kn = ckn; row = t; }
    else         { qk = qkx; qn = xqn; kn = xkn; row = t - S_C; }
    size_t base = (size_t)row * (2 * D) + h * HD + lane * 2;
    float2 qv = __half22float2(*(const __half2*)(qk + base));
    float2 kv = __half22float2(*(const __half2*)(qk + base + D));
    float sq = qv.x * qv.x + qv.y * qv.y;
    float sk = kv.x * kv.x + kv.y * kv.y;
    #pragma unroll
    for (int o = 16; o > 0; o >>= 1) {
        sq += __shfl_xor_sync(0xffffffffu, sq, o);
        sk += __shfl_xor_sync(0xffffffffu, sk, o);
    }
    float rq = rsqrtf(sq * (1.0f / HD) + 1e-6f);
    float rk = rsqrtf(sk * (1.0f / HD) + 1e-6f);
    float2 qw = *(const float2*)(qn + lane * 2);
    float2 kw = *(const float2*)(kn + lane * 2);
    float q0 = qv.x * rq * qw.x, q1 = qv.y * rq * qw.y;
    float k0 = kv.x * rk * kw.x, k1 = kv.y * rk * kw.y;
    float2 f = *(const float2*)(freqs + ((size_t)t * 32 + lane) * 2);
    float cs = f.x, sn = f.y;
    const float QSC = 0.125f * 1.4426950408889634f;
    float oq0 = (q0 * cs - q1 * sn) * QSC;
    float oq1 = (q0 * sn + q1 * cs) * QSC;
    float ok0 = k0 * cs - k1 * sn;
    float ok1 = k0 * sn + k1 * cs;
    size_t off = ((size_t)h * TT + t) * HD + lane * 2;
    *(__half2*)(Q + off)  = __floats2half2_rn(oq0, oq1);
    *(__half2*)(Ko + off) = __floats2half2_rn(ok0, ok1);
}

// ======================================================================
// fp16 tensor-core flash attention, ldmatrix fragments (unchanged R12).
// ======================================================================
#define AHS 72
#define AWS 36
#define ATN_SMEM (6 * 64 * AHS * 2)

__global__ __launch_bounds__(128)
void attn_tc(const __half* __restrict__ Q, const __half* __restrict__ K,
             const __half* __restrict__ V, __half* __restrict__ Y) {
    extern __shared__ uint32_t smw[];
    uint32_t sbase = smem_u32(smw);
    int tid = threadIdx.x, wid = tid >> 5, lane = tid & 31;
    int gid = lane >> 2, tig = lane & 3;
    int bxr = 31 - blockIdx.x;
    int h = blockIdx.y;
    int q0 = bxr * 64;
    const __half* Qh = Q + (size_t)h * TT * HD;
    const __half* Kh = K + (size_t)h * TT * HD;
    const __half* Vh = V + (size_t)h * HD * TT;

    const uint32_t* QsW = smw;
    uint32_t* PwW = smw + 5 * 64 * AWS;

    int lrow = tid >> 1;
    int lblk = tid & 1;

    int tileid = lane >> 3;
    uint32_t poff = (uint32_t)(wid * 16 + (tileid & 1) * 8 + (lane & 7)) * (AHS * 2)
                    + (uint32_t)(tileid >> 1) * 16;
    uint32_t boff = (uint32_t)((tileid >> 1) * 8 + (lane & 7)) * (AHS * 2)
                    + (uint32_t)(tileid & 1) * 16;

    {
        uint32_t qb = sbase;
        uint32_t kb = sbase + (1 * 64 * AWS) * 4;
        uint32_t vb = sbase + (3 * 64 * AWS) * 4;
        #pragma unroll
        for (int j = 0; j < 4; j++) {
            uint32_t so = (lrow * AHS + lblk * 32 + j * 8) * 2;
            cp_async16(qb + so, Qh + (size_t)(q0 + lrow) * HD + lblk * 32 + j * 8);
            cp_async16(kb + so, Kh + (size_t)lrow * HD + lblk * 32 + j * 8);
            cp_async16(vb + so, Vh + (size_t)lrow * TT + lblk * 32 + j * 8);
        }
        CP_COMMIT();
    }
    CP_WAIT0();
    __syncthreads();

    uint32_t qf[4][4];
    int qrow = wid * 16 + gid;
    #pragma unroll
    for (int ks = 0; ks < 4; ks++) {
        qf[ks][0] = QsW[qrow * AWS + ks * 8 + tig];
        qf[ks][1] = QsW[(qrow + 8) * AWS + ks * 8 + tig];
        qf[ks][2] = QsW[qrow * AWS + ks * 8 + tig + 4];
        qf[ks][3] = QsW[(qrow + 8) * AWS + ks * 8 + tig + 4];
    }
    __syncwarp();

    float ofr[8][4];
    #pragma unroll
    for (int ot = 0; ot < 8; ot++)
        #pragma unroll
        for (int e = 0; e < 4; e++) ofr[ot][e] = 0.f;
    float m0r = -INFINITY, m1r = -INFINITY, l0r = 0.f, l1r = 0.f;

    int ntile = bxr + 1;
    for (int kt = 0; kt < ntile; kt++) {
        int k0g = kt * 64;
        int buf = kt & 1;
        uint32_t kbase = sbase + ((1 + buf) * 64 * AWS) * 4;
        uint32_t vbase = sbase + ((3 + buf) * 64 * AWS) * 4;
        uint32_t pbase = sbase + (5 * 64 * AWS) * 4;
        if (kt > 0) { CP_WAIT0(); __syncthreads(); }
        float sacc[8][4];
        #pragma unroll
        for (int nt = 0; nt < 8; nt++)
            #pragma unroll
            for (int e = 0; e < 4; e++) sacc[nt][e] = 0.f;
        #pragma unroll
        for (int ks = 0; ks < 4; ks++) {
            uint32_t bk[4][4];
            #pragma unroll
            for (int kp = 0; kp < 4; kp++)
                ldsm_x4(bk[kp], kbase + boff + (uint32_t)kp * (16 * AHS * 2) + ks * 32);
            #pragma unroll
            for (int kp = 0; kp < 4; kp++) {
                mma_f16(sacc[kp * 2 + 0], qf[ks], &bk[kp][0]);
                mma_f16(sacc[kp * 2 + 1], qf[ks], &bk[kp][2]);
            }
        }
        if (kt + 1 < ntile) {
            uint32_t kb = sbase + ((1 + (buf ^ 1)) * 64 * AWS) * 4;
            uint32_t vb = sbase + ((3 + (buf ^ 1)) * 64 * AWS) * 4;
            const __half* Kp = Kh + (size_t)(k0g + 64) * HD;
            const __half* Vp = Vh + k0g + 64;
            #pragma unroll
            for (int j = 0; j < 4; j++) {
                uint32_t so = (lrow * AHS + lblk * 32 + j * 8) * 2;
                cp_async16(kb + so, Kp + (size_t)lrow * HD + lblk * 32 + j * 8);
                cp_async16(vb + so, Vp + (size_t)lrow * TT + lblk * 32 + j * 8);
            }
        }
        CP_COMMIT();
        if (kt == ntile - 1) {
            int r0 = q0 + wid * 16 + gid;
            #pragma unroll
            for (int nt = 0; nt < 8; nt++) {
                int c0 = k0g + nt * 8 + tig * 2;
                if (c0 > r0)     sacc[nt][0] = -INFINITY;
                if (c0 + 1 > r0) sacc[nt][1] = -INFINITY;
                if (c0 > r0 + 8)     sacc[nt][2] = -INFINITY;
                if (c0 + 1 > r0 + 8) sacc[nt][3] = -INFINITY;
            }
        }
        float tm0 = -INFINITY, tm1 = -INFINITY;
        #pragma unroll
        for (int nt = 0; nt < 8; nt++) {
            tm0 = fmaxf(tm0, fmaxf(sacc[nt][0], sacc[nt][1]));
            tm1 = fmaxf(tm1, fmaxf(sacc[nt][2], sacc[nt][3]));
        }
        #pragma unroll
        for (int o = 1; o < 4; o <<= 1) {
            tm0 = fmaxf(tm0, __shfl_xor_sync(0xffffffffu, tm0, o));
            tm1 = fmaxf(tm1, __shfl_xor_sync(0xffffffffu, tm1, o));
        }
        float nm0 = fmaxf(m0r, tm0), nm1 = fmaxf(m1r, tm1);
        float c0 = ex2f(m0r - nm0), c1 = ex2f(m1r - nm1);
        m0r = nm0; m1r = nm1;
        float ps0 = 0.f, ps1 = 0.f;
        int row0 = wid * 16 + gid, row1 = row0 + 8;
        #pragma unroll
        for (int nt = 0; nt < 8; nt++) {
            float p00 = ex2f(sacc[nt][0] - nm0);
            float p01 = ex2f(sacc[nt][1] - nm0);
            float p10 = ex2f(sacc[nt][2] - nm1);
            float p11 = ex2f(sacc[nt][3] - nm1);
            ps0 += p00 + p01; ps1 += p10 + p11;
            __half2 h0 = __floats2half2_rn(p00, p01);
            __half2 h1 = __floats2half2_rn(p10, p11);
            PwW[row0 * AWS + nt * 4 + tig] = *(uint32_t*)&h0;
            PwW[row1 * AWS + nt * 4 + tig] = *(uint32_t*)&h1;
        }
        #pragma unroll
        for (int o = 1; o < 4; o <<= 1) {
            ps0 += __shfl_xor_sync(0xffffffffu, ps0, o);
            ps1 += __shfl_xor_sync(0xffffffffu, ps1, o);
        }
        l0r = l0r * c0 + ps0;
        l1r = l1r * c1 + ps1;
        #pragma unroll
        for (int ot = 0; ot < 8; ot++) {
            ofr[ot][0] *= c0; ofr[ot][1] *= c0;
            ofr[ot][2] *= c1; ofr[ot][3] *= c1;
        }
        __syncwarp();
        #pragma unroll
        for (int ks = 0; ks < 4; ks++) {
            uint32_t af[4];
            ldsm_x4(af, pbase + poff + ks * 32);
            uint32_t bv[4][4];
            #pragma unroll
            for (int vp = 0; vp < 4; vp++)
                ldsm_x4(bv[vp], vbase + boff + (uint32_t)vp * (16 * AHS * 2) + ks * 32);
            #pragma unroll
            for (int vp = 0; vp < 4; vp++) {
                mma_f16(ofr[vp * 2 + 0], af, &bv[vp][0]);
                mma_f16(ofr[vp * 2 + 1], af, &bv[vp][2]);
            }
        }
        __syncwarp();
    }
    float i0 = 1.0f / l0r, i1 = 1.0f / l1r;
    int t0 = q0 + wid * 16 + gid, t1 = t0 + 8;
    #pragma unroll
    for (int ot = 0; ot < 8; ot++) {
        int col = h * HD + ot * 8 + tig * 2;
        *(__half2*)(Y + (size_t)t0 * D + col) = __floats2half2_rn(ofr[ot][0] * i0, ofr[ot][1] * i0);
        *(__half2*)(Y + (size_t)t1 * D + col) = __floats2half2_rn(ofr[ot][2] * i1, ofr[ot][3] * i1);
    }
}

// ---------------- host launcher ----------------
static inline int nct(int M, int N) { return (M / 128) * (N / 128); }

extern "C" void kernel_launch(void* const* d_in, const int* in_sizes, int n_in,
                              void* d_out, int out_size) {
    const float* x        = (const float*)d_in[0];
    const float* c        = (const float*)d_in[1];
    const float* freqs    = (const float*)d_in[2];
    const float* px_qk_w  = (const float*)d_in[3];
    const float* px_qn    = (const float*)d_in[4];
    const float* px_kn    = (const float*)d_in[5];
    const float* px_v_w   = (const float*)d_in[6];
    const float* px_v_b   = (const float*)d_in[7];
    const float* pc_qk_w  = (const float*)d_in[8];
    const float* pc_qn    = (const float*)d_in[9];
    const float* pc_kn    = (const float*)d_in[10];
    const float* pc_v_w   = (const float*)d_in[11];
    const float* pc_v_b   = (const float*)d_in[12];
    const float* p1_proj_w = (const float*)d_in[13];
    const float* p1_proj_b = (const float*)d_in[14];
    const float* p1_w1    = (const float*)d_in[15];
    const float* p1_b1    = (const float*)d_in[16];
    const float* p1_w3    = (const float*)d_in[17];
    const float* p1_b3    = (const float*)d_in[18];
    const float* p1_w2    = (const float*)d_in[19];
    const float* p1_b2    = (const float*)d_in[20];
    const float* p2_proj_w = (const float*)d_in[21];
    const float* p2_proj_b = (const float*)d_in[22];
    const float* p2_w1    = (const float*)d_in[23];
    const float* p2_b1    = (const float*)d_in[24];
    const float* p2_w3    = (const float*)d_in[25];
    const float* p2_b3    = (const float*)d_in[26];
    const float* p2_w2    = (const float*)d_in[27];
    const float* p2_b2    = (const float*)d_in[28];
    float* out = (float*)d_out;

    float *x1x, *x1c;
    __half *w16, *qk16x, *qk16c, *cln16, *xln16, *q16, *k16, *v16t, *y16;
    __half *h16x, *h16c, *t16x1, *t16c1, *g16x, *g16c;
    cudaGetSymbolAddress((void**)&x1x, g_x1x);
    cudaGetSymbolAddress((void**)&x1c, g_x1c);
    cudaGetSymbolAddress((void**)&w16,   g_w16);
    cudaGetSymbolAddress((void**)&qk16x, g_qk16x);
    cudaGetSymbolAddress((void**)&qk16c, g_qk16c);
    cudaGetSymbolAddress((void**)&cln16, g_cln16);
    cudaGetSymbolAddress((void**)&xln16, g_xln16);
    cudaGetSymbolAddress((void**)&q16,   g_q16);
    cudaGetSymbolAddress((void**)&k16,   g_k16);
    cudaGetSymbolAddress((void**)&v16t,  g_v16t);
    cudaGetSymbolAddress((void**)&y16,   g_y16);
    cudaGetSymbolAddress((void**)&h16x,  g_h16x);
    cudaGetSymbolAddress((void**)&h16c,  g_h16c);
    cudaGetSymbolAddress((void**)&t16x1, g_t16x1);
    cudaGetSymbolAddress((void**)&t16c1, g_t16c1);
    cudaGetSymbolAddress((void**)&g16x,  g_g16x);
    cudaGetSymbolAddress((void**)&g16c,  g_g16c);

    cudaFuncSetAttribute(attn_tc, cudaFuncAttributeMaxDynamicSharedMemorySize, ATN_SMEM);
    cudaFuncSetAttribute(mma_gemm_mj, cudaFuncAttributeMaxDynamicSharedMemorySize, MMG_SMEM);

    // 0) convert weights to fp16 arena
    {
        WJobs W;
        int o = 0;
        W.j[0]  = {pc_qk_w,  w16 + O_PCQK, o}; o += 1024;
        W.j[1]  = {px_qk_w,  w16 + O_PXQK, o}; o += 1024;
        W.j[2]  = {pc_v_w,   w16 + O_PCV,  o}; o += 512;
        W.j[3]  = {px_v_w,   w16 + O_PXV,  o}; o += 512;
        W.j[4]  = {p1_proj_w, w16 + O_P1P, o}; o += 512;
        W.j[5]  = {p2_proj_w, w16 + O_P2P, o}; o += 512;
        W.j[6]  = {p1_w1,    w16 + O_P1W1, o}; o += 2048;
        W.j[7]  = {p1_w3,    w16 + O_P1W3, o}; o += 2048;
        W.j[8]  = {p2_w1,    w16 + O_P2W1, o}; o += 2048;
        W.j[9]  = {p2_w3,    w16 + O_P2W3, o}; o += 2048;
        W.j[10] = {p1_w2,    w16 + O_P1W2, o}; o += 2048;
        W.j[11] = {p2_w2,    w16 + O_P2W2, o}; o += 2048;
        cvt16<<<o, 256>>>(W);
    }

    // 1) LayerNorm both streams -> fp16
    ln2_kernel<<<L_X + S_C, 256>>>(x, xln16, L_X, c, cln16);

    // 2) QKV GEMMs; qk fp16 out, V fp16 dim-major
    {
        GJobs J; J.n = 4;
        int o = 0;
        J.j[0] = {cln16, w16 + O_PCQK, nullptr, nullptr, qk16c, 2 * D, D, o, 2, 0};  o += nct(S_C, 2 * D);
        J.j[1] = {cln16, w16 + O_PCV,  pc_v_b,  nullptr, v16t,  D,     D, o, 1, 0};  o += nct(S_C, D);
        J.j[2] = {xln16, w16 + O_PXQK, nullptr, nullptr, qk16x, 2 * D, D, o, 2, 0};  o += nct(L_X, 2 * D);
        J.j[3] = {xln16, w16 + O_PXV,  px_v_b,  nullptr, v16t,  D,     D, o, 1, S_C}; o += nct(L_X, D);
        mma_gemm_mj<<<o, 128, MMG_SMEM>>>(J);
    }
    qk_finish_all<<<TT * H / 8, 256>>>(qk16c, qk16x, pc_qn, pc_kn, px_qn, px_kn, freqs, q16, k16);

    // 3) causal attention -> y fp16
    attn_tc<<<dim3(32, H), 128, ATN_SMEM>>>(q16, k16, v16t, y16);

    // 4) output projections (batched)
    const __half* yx16 = y16 + (size_t)S_C * D;
    {
        GJobs J; J.n = 2;
        int o = 0;
        J.j[0] = {yx16, w16 + O_P1P, p1_proj_b, x, x1x, D, D, o, 0, 0}; o += nct(L_X, D);
        J.j[1] = {y16,  w16 + O_P2P, p2_proj_b, c, x1c, D, D, o, 0, 0}; o += nct(S_C, D);
        J.j[2] = J.j[0]; J.j[3] = J.j[0];
        mma_gemm_mj<<<o, 128, MMG_SMEM>>>(J);
    }
    ln2_kernel<<<L_X + S_C, 256>>>(x1x, h16x, L_X, x1c, h16c);

    // 5a) w1 (batched) -> t1 fp16
    {
        GJobs J; J.n = 2;
        int o = 0;
        J.j[0] = {h16x, w16 + O_P1W1, p1_b1, nullptr, t16x1, FF, D, o, 2, 0}; o += nct(L_X, FF);
        J.j[1] = {h16c, w16 + O_P2W1, p2_b1, nullptr, t16c1, FF, D, o, 2, 0}; o += nct(S_C, FF);
        J.j[2] = J.j[0]; J.j[3] = J.j[0];
        mma_gemm_mj<<<o, 128, MMG_SMEM>>>(J);
    }
    // 5b) w3 with fused SiLU gate -> g fp16
    {
        GJobs J; J.n = 2;
        int o = 0;
        J.j[0] = {h16x, w16 + O_P1W3, p1_b3, (const float*)t16x1, g16x, FF, D, o, 3, 0}; o += nct(L_X, FF);
        J.j[1] = {h16c, w16 + O_P2W3, p2_b3, (const float*)t16c1, g16c, FF, D, o, 3, 0}; o += nct(S_C, FF);
        J.j[2] = J.j[0]; J.j[3] = J.j[0];
        mma_gemm_mj<<<o, 128, MMG_SMEM>>>(J);
    }

    // 6) w2 (batched)
    {
        GJobs J; J.n = 2;
        int o = 0;
        J.j[0] = {g16x, w16 + O_P1W2, p1_b2, x1x, out,                   D, FF, o, 0, 0}; o += nct(L_X, D);
        J.j[1] = {g16c, w16 + O_P2W2, p2_b2, x1c, out + (size_t)L_X * D, D, FF, o, 0, 0}; o += nct(S_C, D);
        J.j[2] = J.j[0]; J.j[3] = J.j[0];
        mma_gemm_mj<<<o, 128, MMG_SMEM>>>(J);
    }
}

// round 15
// speedup vs baseline: 1.1574x; 1.0793x over previous
#include <cuda_runtime.h>
#include <cuda_fp16.h>
#include <cstdint>
#include <math.h>

// ---------------- problem constants ----------------
#define L_X   1536
#define S_C   512
#define TT    2048          // L_X + S_C
#define D     1024
#define H     16
#define HD    64
#define FF    4096

// ---------------- scratch (device globals; no cudaMalloc allowed) ----------
__device__ float g_x1x[L_X * D];
__device__ float g_x1c[S_C * D];

// fp16 buffers
__device__ __half g_w16  [33554432];
__device__ __half g_qk16x[L_X * 2 * D];
__device__ __half g_qk16c[S_C * 2 * D];
__device__ __half g_cln16[S_C * D];
__device__ __half g_xln16[L_X * D];
__device__ __half g_q16  [H * TT * HD];
__device__ __half g_k16  [H * TT * HD];
__device__ __half g_v16t [H * HD * TT];
__device__ __half g_y16  [TT * D];
__device__ __half g_h16x [L_X * D];
__device__ __half g_h16c [S_C * D];
__device__ __half g_t16x1[L_X * FF];
__device__ __half g_t16x3[L_X * FF];
__device__ __half g_t16c1[S_C * FF];
__device__ __half g_t16c3[S_C * FF];
__device__ __half g_g16x [L_X * FF];
__device__ __half g_g16c [S_C * FF];

// arena offsets (halves)
#define O_PCQK 0
#define O_PXQK 2097152
#define O_PCV  4194304
#define O_PXV  5242880
#define O_P1P  6291456
#define O_P2P  7340032
#define O_P1W1 8388608
#define O_P1W3 12582912
#define O_P2W1 16777216
#define O_P2W3 20971520
#define O_P1W2 25165824
#define O_P2W2 29360128

// ---------------- utils ----------------
__device__ __forceinline__ float warpSum(float v) {
    #pragma unroll
    for (int o = 16; o > 0; o >>= 1) v += __shfl_xor_sync(0xffffffffu, v, o);
    return v;
}
__device__ __forceinline__ float ex2f(float x) {
    float y;
    asm("ex2.approx.f32 %0, %1;" : "=f"(y) : "f"(x));
    return y;
}
__device__ __forceinline__ void mma_f16(float* d, const uint32_t* a, const uint32_t* b) {
    asm volatile(
        "mma.sync.aligned.m16n8k16.row.col.f32.f16.f16.f32 "
        "{%0,%1,%2,%3}, {%4,%5,%6,%7}, {%8,%9}, {%0,%1,%2,%3};"
        : "+f"(d[0]), "+f"(d[1]), "+f"(d[2]), "+f"(d[3])
        : "r"(a[0]), "r"(a[1]), "r"(a[2]), "r"(a[3]), "r"(b[0]), "r"(b[1]));
}
__device__ __forceinline__ void ldsm_x4(uint32_t* r, uint32_t addr) {
    asm volatile("ldmatrix.sync.aligned.m8n8.x4.shared.b16 {%0,%1,%2,%3}, [%4];"
        : "=r"(r[0]), "=r"(r[1]), "=r"(r[2]), "=r"(r[3]) : "r"(addr));
}
__device__ __forceinline__ uint32_t smem_u32(const void* p) {
    uint32_t a;
    asm("{ .reg .u64 t; cvta.to.shared.u64 t, %1; cvt.u32.u64 %0, t; }" : "=r"(a) : "l"(p));
    return a;
}
__device__ __forceinline__ void cp_async16(uint32_t saddr, const void* gaddr) {
    asm volatile("cp.async.cg.shared.global [%0], [%1], 16;" :: "r"(saddr), "l"(gaddr));
}
#define CP_COMMIT() asm volatile("cp.async.commit_group;" ::: "memory")
#define CP_WAIT0()  asm volatile("cp.async.wait_group 0;" ::: "memory")
#define CP_WAIT1()  asm volatile("cp.async.wait_group 1;" ::: "memory")

// ---------------- fused prologue: weight cvt (12 jobs) + LayerNorm ------
struct WJob { const float* src; __half* dst; int off; };
struct WJobs { WJob j[12]; };

#define CVT_BLKS 16384

__global__ __launch_bounds__(256)
void prologue(WJobs J,
              const float* __restrict__ lx, __half* __restrict__ lox, int rows0,
              const float* __restrict__ lc, __half* __restrict__ loc) {
    if ((int)blockIdx.x < CVT_BLKS) {
        int ji = 0;
        #pragma unroll
        for (int t = 1; t < 12; t++) if ((int)blockIdx.x >= J.j[t].off) ji = t;
        size_t idx = ((size_t)(blockIdx.x - J.j[ji].off) * 256 + threadIdx.x) * 8;
        const float4* s = (const float4*)(J.j[ji].src + idx);
        float4 v0 = s[0], v1 = s[1];
        __half2* d = (__half2*)(J.j[ji].dst + idx);
        d[0] = __floats2half2_rn(v0.x, v0.y);
        d[1] = __floats2half2_rn(v0.z, v0.w);
        d[2] = __floats2half2_rn(v1.x, v1.y);
        d[3] = __floats2half2_rn(v1.z, v1.w);
        return;
    }
    int row = blockIdx.x - CVT_BLKS;
    const float* x;
    __half* o;
    if (row < rows0) { x = lx + (size_t)row * D; o = lox + (size_t)row * D; }
    else             { x = lc + (size_t)(row - rows0) * D; o = loc + (size_t)(row - rows0) * D; }
    float4 v = *(const float4*)(x + threadIdx.x * 4);
    float s = v.x + v.y + v.z + v.w;
    float ss = v.x * v.x + v.y * v.y + v.z * v.z + v.w * v.w;
    __shared__ float shs[8], shss[8];
    float ws = warpSum(s), wss = warpSum(ss);
    int w = threadIdx.x >> 5;
    if ((threadIdx.x & 31) == 0) { shs[w] = ws; shss[w] = wss; }
    __syncthreads();
    float ts = 0.f, tss = 0.f;
    #pragma unroll
    for (int i = 0; i < 8; i++) { ts += shs[i]; tss += shss[i]; }
    float mean = ts * (1.0f / D);
    float var  = tss * (1.0f / D) - mean * mean;
    float inv  = rsqrtf(var + 1e-6f);
    __half2* o2 = (__half2*)(o + threadIdx.x * 4);
    o2[0] = __floats2half2_rn((v.x - mean) * inv, (v.y - mean) * inv);
    o2[1] = __floats2half2_rn((v.z - mean) * inv, (v.w - mean) * inv);
}

// ---------------- LayerNorm pair -> fp16 (row cached in registers) -----
__global__ __launch_bounds__(256)
void ln2_kernel(const float* __restrict__ in0, __half* __restrict__ out0,
                int rows0,
                const float* __restrict__ in1, __half* __restrict__ out1) {
    int row = blockIdx.x;
    const float* x;
    __half* o;
    if (row < rows0) { x = in0 + (size_t)row * D; o = out0 + (size_t)row * D; }
    else             { x = in1 + (size_t)(row - rows0) * D; o = out1 + (size_t)(row - rows0) * D; }
    float4 v = *(const float4*)(x + threadIdx.x * 4);
    float s = v.x + v.y + v.z + v.w;
    float ss = v.x * v.x + v.y * v.y + v.z * v.z + v.w * v.w;
    __shared__ float shs[8], shss[8];
    float ws = warpSum(s), wss = warpSum(ss);
    int w = threadIdx.x >> 5;
    if ((threadIdx.x & 31) == 0) { shs[w] = ws; shss[w] = wss; }
    __syncthreads();
    float ts = 0.f, tss = 0.f;
    #pragma unroll
    for (int i = 0; i < 8; i++) { ts += shs[i]; tss += shss[i]; }
    float mean = ts * (1.0f / D);
    float var  = tss * (1.0f / D) - mean * mean;
    float inv  = rsqrtf(var + 1e-6f);
    __half2* o2 = (__half2*)(o + threadIdx.x * 4);
    o2[0] = __floats2half2_rn((v.x - mean) * inv, (v.y - mean) * inv);
    o2[1] = __floats2half2_rn((v.z - mean) * inv, (v.w - mean) * inv);
}

// ======================================================================
// Multi-job fp16 GEMM (m16n8k16), K-chunk 32, 3-stage cp.async, ldmatrix.
// (R12 configuration: 61.4KB smem -> 3 CTAs/SM.)
// mode 0: fp32 row-major (+resid). mode 1: fp16 V dim-major. mode 2: fp16 C.
// ======================================================================
struct GJob {
    const __half* A; const __half* B; const float* bias; const float* resid;
    void* C; int N, K, off, mode, t_off;
};
struct GJobs { GJob j[4]; int n; };

#define HST 20
#define HBUF (128 * HST)
#define MMG_SMEM (3 * 2 * HBUF * 4)

__global__ __launch_bounds__(128)
void mma_gemm_mj(GJobs jobs) {
    int ji = 0;
    if (jobs.n > 1 && (int)blockIdx.x >= jobs.j[1].off) ji = 1;
    if (jobs.n > 2 && (int)blockIdx.x >= jobs.j[2].off) ji = 2;
    if (jobs.n > 3 && (int)blockIdx.x >= jobs.j[3].off) ji = 3;
    const __half* A = jobs.j[ji].A;
    const __half* B = jobs.j[ji].B;
    const float* bias = jobs.j[ji].bias;
    const float* resid = jobs.j[ji].resid;
    void* C = jobs.j[ji].C;
    int N = jobs.j[ji].N, K = jobs.j[ji].K;
    int mode = jobs.j[ji].mode, t_off = jobs.j[ji].t_off;
    int lid0 = blockIdx.x - jobs.j[ji].off;
    int nbx = N >> 7;
    int by = lid0 / nbx, bx = lid0 - by * nbx;
    int m0 = by * 128, n0 = bx * 128;

    extern __shared__ uint32_t smw[];
    uint32_t sbase = smem_u32(smw);
    int tid = threadIdx.x;
    int wid = tid >> 5, lane = tid & 31;
    int gid = lane >> 2, tig = lane & 3;
    int warp_m = wid >> 1, warp_n = wid & 1;

    float acc[4][8][4];
    #pragma unroll
    for (int mt = 0; mt < 4; mt++)
        #pragma unroll
        for (int nt = 0; nt < 8; nt++)
            #pragma unroll
            for (int e = 0; e < 4; e++) acc[mt][nt][e] = 0.f;

    const int nchunk = K >> 5;
    int lrow = tid >> 2;
    int lblk = tid & 3;

    int tileid = lane >> 3;
    uint32_t aoff = (uint32_t)(warp_m * 64 + (tileid & 1) * 8 + (lane & 7)) * 80
                    + (uint32_t)(tileid >> 1) * 16;
    uint32_t boff = (uint32_t)(warp_n * 64 + (tileid >> 1) * 8 + (lane & 7)) * 80
                    + (uint32_t)(tileid & 1) * 16;

    #pragma unroll
    for (int pc = 0; pc < 2; pc++) {
        const __half* Ap = A + (size_t)m0 * K + pc * 32 + lblk * 8;
        const __half* Bp = B + (size_t)n0 * K + pc * 32 + lblk * 8;
        uint32_t sA = sbase + pc * 2 * HBUF * 4;
        uint32_t sB = sA + HBUF * 4;
        #pragma unroll
        for (int l = 0; l < 4; l++) {
            int r = lrow + l * 32;
            uint32_t so = (r * HST + lblk * 4) * 4;
            cp_async16(sA + so, Ap + (size_t)r * K);
            cp_async16(sB + so, Bp + (size_t)r * K);
        }
        CP_COMMIT();
    }

    int st = 0;
    for (int i = 0; i < nchunk; i++) {
        CP_WAIT1();
        __syncthreads();
        if (i + 2 < nchunk) {
            int ps = st + 2; if (ps >= 3) ps -= 3;
            const __half* Ap = A + (size_t)m0 * K + (i + 2) * 32 + lblk * 8;
            const __half* Bp = B + (size_t)n0 * K + (i + 2) * 32 + lblk * 8;
            uint32_t sA = sbase + ps * 2 * HBUF * 4;
            uint32_t sB = sA + HBUF * 4;
            #pragma unroll
            for (int l = 0; l < 4; l++) {
                int r = lrow + l * 32;
                uint32_t so = (r * HST + lblk * 4) * 4;
                cp_async16(sA + so, Ap + (size_t)r * K);
                cp_async16(sB + so, Bp + (size_t)r * K);
            }
        }
        CP_COMMIT();
        uint32_t stA = sbase + st * 2 * HBUF * 4;
        uint32_t stB = stA + HBUF * 4;
        #pragma unroll
        for (int s = 0; s < 2; s++) {
            uint32_t kbyte = s * 32;
            uint32_t af[4][4], bf[4][4];
            #pragma unroll
            for (int mt = 0; mt < 4; mt++)
                ldsm_x4(af[mt], stA + aoff + (uint32_t)mt * (16 * 80) + kbyte);
            #pragma unroll
            for (int ntp = 0; ntp < 4; ntp++)
                ldsm_x4(bf[ntp], stB + boff + (uint32_t)ntp * (16 * 80) + kbyte);
            #pragma unroll
            for (int mt = 0; mt < 4; mt++)
                #pragma unroll
                for (int ntp = 0; ntp < 4; ntp++) {
                    mma_f16(acc[mt][ntp * 2 + 0], af[mt], &bf[ntp][0]);
                    mma_f16(acc[mt][ntp * 2 + 1], af[mt], &bf[ntp][2]);
                }
        }
        st++; if (st >= 3) st = 0;
    }

    #pragma unroll
    for (int mt = 0; mt < 4; mt++) {
        #pragma unroll
        for (int nt = 0; nt < 8; nt++) {
            int row = m0 + warp_m * 64 + mt * 16 + gid;
            int col = n0 + warp_n * 64 + nt * 8 + tig * 2;
            #pragma unroll
            for (int half = 0; half < 2; half++) {
                int r = row + half * 8;
                float2 v = make_float2(acc[mt][nt][half * 2], acc[mt][nt][half * 2 + 1]);
                if (bias) {
                    float2 bv2 = *(const float2*)(bias + col);
                    v.x += bv2.x; v.y += bv2.y;
                }
                if (mode == 0) {
                    float* Cf = (float*)C;
                    size_t off = (size_t)r * N + col;
                    if (resid) {
                        float2 rv = *(const float2*)(resid + off);
                        v.x += rv.x; v.y += rv.y;
                    }
                    *(float2*)(Cf + off) = v;
                } else if (mode == 1) {
                    __half* Ch = (__half*)C;
                    int hh = col >> 6, dd = col & 63;
                    Ch[((size_t)hh * HD + dd) * TT + t_off + r]     = __float2half_rn(v.x);
                    Ch[((size_t)hh * HD + dd + 1) * TT + t_off + r] = __float2half_rn(v.y);
                } else {
                    __half* Ch = (__half*)C;
                    *(__half2*)(Ch + (size_t)r * N + col) = __floats2half2_rn(v.x, v.y);
                }
            }
        }
    }
}

// ---------------- qk finish: warp per (t,h), lane owns RoPE pair --------
__global__ __launch_bounds__(256)
void qk_finish_all(const __half* __restrict__ qkc, const __half* __restrict__ qkx,
                   const float* __restrict__ cqn, const float* __restrict__ ckn,
                   const float* __restrict__ xqn, const float* __restrict__ xkn,
                   const float* __restrict__ freqs,
                   __half* __restrict__ Q, __half* __restrict__ Ko) {
    int gidx = blockIdx.x * 8 + (threadIdx.x >> 5);
    int lane = threadIdx.x & 31;
    int t = gidx >> 4;
    int h = gidx & 15;
    const __half* qk; const float* qn; const float* kn; int row;
    if (t < S_C) { qk = qkc; qn = cqn; kn = ckn; row = t; }
    else         { qk = qkx; qn = xqn; kn = xkn; row = t - S_C; }
    size_t base = (size_t)row * (2 * D) + h * HD + lane * 2;
    float2 qv = __half22float2(*(const __half2*)(qk + base));
    float2 kv = __half22float2(*(const __half2*)(qk + base + D));
    float sq = qv.x * qv.x + qv.y * qv.y;
    float sk = kv.x * kv.x + kv.y * kv.y;
    #pragma unroll
    for (int o = 16; o > 0; o >>= 1) {
        sq += __shfl_xor_sync(0xffffffffu, sq, o);
        sk += __shfl_xor_sync(0xffffffffu, sk, o);
    }
    float rq = rsqrtf(sq * (1.0f / HD) + 1e-6f);
    float rk = rsqrtf(sk * (1.0f / HD) + 1e-6f);
    float2 qw = *(const float2*)(qn + lane * 2);
    float2 kw = *(const float2*)(kn + lane * 2);
    float q0 = qv.x * rq * qw.x, q1 = qv.y * rq * qw.y;
    float k0 = kv.x * rk * kw.x, k1 = kv.y * rk * kw.y;
    float2 f = *(const float2*)(freqs + ((size_t)t * 32 + lane) * 2);
    float cs = f.x, sn = f.y;
    const float QSC = 0.125f * 1.4426950408889634f;
    float oq0 = (q0 * cs - q1 * sn) * QSC;
    float oq1 = (q0 * sn + q1 * cs) * QSC;
    float ok0 = k0 * cs - k1 * sn;
    float ok1 = k0 * sn + k1 * cs;
    size_t off = ((size_t)h * TT + t) * HD + lane * 2;
    *(__half2*)(Q + off)  = __floats2half2_rn(oq0, oq1);
    *(__half2*)(Ko + off) = __floats2half2_rn(ok0, ok1);
}

// ======================================================================
// fp16 tensor-core flash attention, ldmatrix fragments (R12 exact).
// ======================================================================
#define AHS 72
#define AWS 36
#define ATN_SMEM (6 * 64 * AHS * 2)

__global__ __launch_bounds__(128)
void attn_tc(const __half* __restrict__ Q, const __half* __restrict__ K,
             const __half* __restrict__ V, __half* __restrict__ Y) {
    extern __shared__ uint32_t smw[];
    uint32_t sbase = smem_u32(smw);
    int tid = threadIdx.x, wid = tid >> 5, lane = tid & 31;
    int gid = lane >> 2, tig = lane & 3;
    int bxr = 31 - blockIdx.x;
    int h = blockIdx.y;
    int q0 = bxr * 64;
    const __half* Qh = Q + (size_t)h * TT * HD;
    const __half* Kh = K + (size_t)h * TT * HD;
    const __half* Vh = V + (size_t)h * HD * TT;

    const uint32_t* QsW = smw;
    uint32_t* PwW = smw + 5 * 64 * AWS;

    int lrow = tid >> 1;
    int lblk = tid & 1;

    int tileid = lane >> 3;
    uint32_t poff = (uint32_t)(wid * 16 + (tileid & 1) * 8 + (lane & 7)) * (AHS * 2)
                    + (uint32_t)(tileid >> 1) * 16;
    uint32_t boff = (uint32_t)((tileid >> 1) * 8 + (lane & 7)) * (AHS * 2)
                    + (uint32_t)(tileid & 1) * 16;

    {
        uint32_t qb = sbase;
        uint32_t kb = sbase + (1 * 64 * AWS) * 4;
        uint32_t vb = sbase + (3 * 64 * AWS) * 4;
        #pragma unroll
        for (int j = 0; j < 4; j++) {
            uint32_t so = (lrow * AHS + lblk * 32 + j * 8) * 2;
            cp_async16(qb + so, Qh + (size_t)(q0 + lrow) * HD + lblk * 32 + j * 8);
            cp_async16(kb + so, Kh + (size_t)lrow * HD + lblk * 32 + j * 8);
            cp_async16(vb + so, Vh + (size_t)lrow * TT + lblk * 32 + j * 8);
        }
        CP_COMMIT();
    }
    CP_WAIT0();
    __syncthreads();

    uint32_t qf[4][4];
    int qrow = wid * 16 + gid;
    #pragma unroll
    for (int ks = 0; ks < 4; ks++) {
        qf[ks][0] = QsW[qrow * AWS + ks * 8 + tig];
        qf[ks][1] = QsW[(qrow + 8) * AWS + ks * 8 + tig];
        qf[ks][2] = QsW[qrow * AWS + ks * 8 + tig + 4];
        qf[ks][3] = QsW[(qrow + 8) * AWS + ks * 8 + tig + 4];
    }
    __syncwarp();

    float ofr[8][4];
    #pragma unroll
    for (int ot = 0; ot < 8; ot++)
        #pragma unroll
        for (int e = 0; e < 4; e++) ofr[ot][e] = 0.f;
    float m0r = -INFINITY, m1r = -INFINITY, l0r = 0.f, l1r = 0.f;

    int ntile = bxr + 1;
    for (int kt = 0; kt < ntile; kt++) {
        int k0g = kt * 64;
        int buf = kt & 1;
        uint32_t kbase = sbase + ((1 + buf) * 64 * AWS) * 4;
        uint32_t vbase = sbase + ((3 + buf) * 64 * AWS) * 4;
        uint32_t pbase = sbase + (5 * 64 * AWS) * 4;
        if (kt > 0) { CP_WAIT0(); __syncthreads(); }
        float sacc[8][4];
        #pragma unroll
        for (int nt = 0; nt < 8; nt++)
            #pragma unroll
            for (int e = 0; e < 4; e++) sacc[nt][e] = 0.f;
        #pragma unroll
        for (int ks = 0; ks < 4; ks++) {
            uint32_t bk[4][4];
            #pragma unroll
            for (int kp = 0; kp < 4; kp++)
                ldsm_x4(bk[kp], kbase + boff + (uint32_t)kp * (16 * AHS * 2) + ks * 32);
            #pragma unroll
            for (int kp = 0; kp < 4; kp++) {
                mma_f16(sacc[kp * 2 + 0], qf[ks], &bk[kp][0]);
                mma_f16(sacc[kp * 2 + 1], qf[ks], &bk[kp][2]);
            }
        }
        if (kt + 1 < ntile) {
            uint32_t kb = sbase + ((1 + (buf ^ 1)) * 64 * AWS) * 4;
            uint32_t vb = sbase + ((3 + (buf ^ 1)) * 64 * AWS) * 4;
            const __half* Kp = Kh + (size_t)(k0g + 64) * HD;
            const __half* Vp = Vh + k0g + 64;
            #pragma unroll
            for (int j = 0; j < 4; j++) {
                uint32_t so = (lrow * AHS + lblk * 32 + j * 8) * 2;
                cp_async16(kb + so, Kp + (size_t)lrow * HD + lblk * 32 + j * 8);
                cp_async16(vb + so, Vp + (size_t)lrow * TT + lblk * 32 + j * 8);
            }
        }
        CP_COMMIT();
        if (kt == ntile - 1) {
            int r0 = q0 + wid * 16 + gid;
            #pragma unroll
            for (int nt = 0; nt < 8; nt++) {
                int c0 = k0g + nt * 8 + tig * 2;
                if (c0 > r0)     sacc[nt][0] = -INFINITY;
                if (c0 + 1 > r0) sacc[nt][1] = -INFINITY;
                if (c0 > r0 + 8)     sacc[nt][2] = -INFINITY;
                if (c0 + 1 > r0 + 8) sacc[nt][3] = -INFINITY;
            }
        }
        float tm0 = -INFINITY, tm1 = -INFINITY;
        #pragma unroll
        for (int nt = 0; nt < 8; nt++) {
            tm0 = fmaxf(tm0, fmaxf(sacc[nt][0], sacc[nt][1]));
            tm1 = fmaxf(tm1, fmaxf(sacc[nt][2], sacc[nt][3]));
        }
        #pragma unroll
        for (int o = 1; o < 4; o <<= 1) {
            tm0 = fmaxf(tm0, __shfl_xor_sync(0xffffffffu, tm0, o));
            tm1 = fmaxf(tm1, __shfl_xor_sync(0xffffffffu, tm1, o));
        }
        float nm0 = fmaxf(m0r, tm0), nm1 = fmaxf(m1r, tm1);
        float c0 = ex2f(m0r - nm0), c1 = ex2f(m1r - nm1);
        m0r = nm0; m1r = nm1;
        float ps0 = 0.f, ps1 = 0.f;
        int row0 = wid * 16 + gid, row1 = row0 + 8;
        #pragma unroll
        for (int nt = 0; nt < 8; nt++) {
            float p00 = ex2f(sacc[nt][0] - nm0);
            float p01 = ex2f(sacc[nt][1] - nm0);
            float p10 = ex2f(sacc[nt][2] - nm1);
            float p11 = ex2f(sacc[nt][3] - nm1);
            ps0 += p00 + p01; ps1 += p10 + p11;
            __half2 h0 = __floats2half2_rn(p00, p01);
            __half2 h1 = __floats2half2_rn(p10, p11);
            PwW[row0 * AWS + nt * 4 + tig] = *(uint32_t*)&h0;
            PwW[row1 * AWS + nt * 4 + tig] = *(uint32_t*)&h1;
        }
        #pragma unroll
        for (int o = 1; o < 4; o <<= 1) {
            ps0 += __shfl_xor_sync(0xffffffffu, ps0, o);
            ps1 += __shfl_xor_sync(0xffffffffu, ps1, o);
        }
        l0r = l0r * c0 + ps0;
        l1r = l1r * c1 + ps1;
        #pragma unroll
        for (int ot = 0; ot < 8; ot++) {
            ofr[ot][0] *= c0; ofr[ot][1] *= c0;
            ofr[ot][2] *= c1; ofr[ot][3] *= c1;
        }
        __syncwarp();
        #pragma unroll
        for (int ks = 0; ks < 4; ks++) {
            uint32_t af[4];
            ldsm_x4(af, pbase + poff + ks * 32);
            uint32_t bv[4][4];
            #pragma unroll
            for (int vp = 0; vp < 4; vp++)
                ldsm_x4(bv[vp], vbase + boff + (uint32_t)vp * (16 * AHS * 2) + ks * 32);
            #pragma unroll
            for (int vp = 0; vp < 4; vp++) {
                mma_f16(ofr[vp * 2 + 0], af, &bv[vp][0]);
                mma_f16(ofr[vp * 2 + 1], af, &bv[vp][2]);
            }
        }
        __syncwarp();
    }
    float i0 = 1.0f / l0r, i1 = 1.0f / l1r;
    int t0 = q0 + wid * 16 + gid, t1 = t0 + 8;
    #pragma unroll
    for (int ot = 0; ot < 8; ot++) {
        int col = h * HD + ot * 8 + tig * 2;
        *(__half2*)(Y + (size_t)t0 * D + col) = __floats2half2_rn(ofr[ot][0] * i0, ofr[ot][1] * i0);
        *(__half2*)(Y + (size_t)t1 * D + col) = __floats2half2_rn(ofr[ot][2] * i1, ofr[ot][3] * i1);
    }
}

// ---------------- SiLU gate fp16 -> fp16 (fast sigmoid) ----------------
__global__ __launch_bounds__(256)
void silu_all(const __half* __restrict__ a0, const __half* __restrict__ b0,
              __half* __restrict__ g0, int n0,
              const __half* __restrict__ a1, const __half* __restrict__ b1,
              __half* __restrict__ g1, int n1) {
    const float L2E = 1.4426950408889634f;
    int i = blockIdx.x * 256 + threadIdx.x;
    int h0 = n0 >> 1;
    if (i < h0) {
        __half2 av = ((const __half2*)a0)[i];
        __half2 bv = ((const __half2*)b0)[i];
        float x0 = __half2float(__low2half(av)), x1 = __half2float(__high2half(av));
        float s0 = x0 / (1.0f + ex2f(-x0 * L2E)) * __half2float(__low2half(bv));
        float s1 = x1 / (1.0f + ex2f(-x1 * L2E)) * __half2float(__high2half(bv));
        ((__half2*)g0)[i] = __floats2half2_rn(s0, s1);
    } else if (i < h0 + (n1 >> 1)) {
        int j = i - h0;
        __half2 av = ((const __half2*)a1)[j];
        __half2 bv = ((const __half2*)b1)[j];
        float x0 = __half2float(__low2half(av)), x1 = __half2float(__high2half(av));
        float s0 = x0 / (1.0f + ex2f(-x0 * L2E)) * __half2float(__low2half(bv));
        float s1 = x1 / (1.0f + ex2f(-x1 * L2E)) * __half2float(__high2half(bv));
        ((__half2*)g1)[j] = __floats2half2_rn(s0, s1);
    }
}

// ---------------- host launcher ----------------
static inline int nct(int M, int N) { return (M / 128) * (N / 128); }

extern "C" void kernel_launch(void* const* d_in, const int* in_sizes, int n_in,
                              void* d_out, int out_size) {
    const float* x        = (const float*)d_in[0];
    const float* c        = (const float*)d_in[1];
    const float* freqs    = (const float*)d_in[2];
    const float* px_qk_w  = (const float*)d_in[3];
    const float* px_qn    = (const float*)d_in[4];
    const float* px_kn    = (const float*)d_in[5];
    const float* px_v_w   = (const float*)d_in[6];
    const float* px_v_b   = (const float*)d_in[7];
    const float* pc_qk_w  = (const float*)d_in[8];
    const float* pc_qn    = (const float*)d_in[9];
    const float* pc_kn    = (const float*)d_in[10];
    const float* pc_v_w   = (const float*)d_in[11];
    const float* pc_v_b   = (const float*)d_in[12];
    const float* p1_proj_w = (const float*)d_in[13];
    const float* p1_proj_b = (const float*)d_in[14];
    const float* p1_w1    = (const float*)d_in[15];
    const float* p1_b1    = (const float*)d_in[16];
    const float* p1_w3    = (const float*)d_in[17];
    const float* p1_b3    = (const float*)d_in[18];
    const float* p1_w2    = (const float*)d_in[19];
    const float* p1_b2    = (const float*)d_in[20];
    const float* p2_proj_w = (const float*)d_in[21];
    const float* p2_proj_b = (const float*)d_in[22];
    const float* p2_w1    = (const float*)d_in[23];
    const float* p2_b1    = (const float*)d_in[24];
    const float* p2_w3    = (const float*)d_in[25];
    const float* p2_b3    = (const float*)d_in[26];
    const float* p2_w2    = (const float*)d_in[27];
    const float* p2_b2    = (const float*)d_in[28];
    float* out = (float*)d_out;

    float *x1x, *x1c;
    __half *w16, *qk16x, *qk16c, *cln16, *xln16, *q16, *k16, *v16t, *y16;
    __half *h16x, *h16c, *t16x1, *t16x3, *t16c1, *t16c3, *g16x, *g16c;
    cudaGetSymbolAddress((void**)&x1x, g_x1x);
    cudaGetSymbolAddress((void**)&x1c, g_x1c);
    cudaGetSymbolAddress((void**)&w16,   g_w16);
    cudaGetSymbolAddress((void**)&qk16x, g_qk16x);
    cudaGetSymbolAddress((void**)&qk16c, g_qk16c);
    cudaGetSymbolAddress((void**)&cln16, g_cln16);
    cudaGetSymbolAddress((void**)&xln16, g_xln16);
    cudaGetSymbolAddress((void**)&q16,   g_q16);
    cudaGetSymbolAddress((void**)&k16,   g_k16);
    cudaGetSymbolAddress((void**)&v16t,  g_v16t);
    cudaGetSymbolAddress((void**)&y16,   g_y16);
    cudaGetSymbolAddress((void**)&h16x,  g_h16x);
    cudaGetSymbolAddress((void**)&h16c,  g_h16c);
    cudaGetSymbolAddress((void**)&t16x1, g_t16x1);
    cudaGetSymbolAddress((void**)&t16x3, g_t16x3);
    cudaGetSymbolAddress((void**)&t16c1, g_t16c1);
    cudaGetSymbolAddress((void**)&t16c3, g_t16c3);
    cudaGetSymbolAddress((void**)&g16x,  g_g16x);
    cudaGetSymbolAddress((void**)&g16c,  g_g16c);

    cudaFuncSetAttribute(attn_tc, cudaFuncAttributeMaxDynamicSharedMemorySize, ATN_SMEM);
    cudaFuncSetAttribute(mma_gemm_mj, cudaFuncAttributeMaxDynamicSharedMemorySize, MMG_SMEM);

    // 0) fused prologue: weight cvt + LayerNorm both streams
    {
        WJobs W;
        int o = 0;
        W.j[0]  = {pc_qk_w,  w16 + O_PCQK, o}; o += 1024;
        W.j[1]  = {px_qk_w,  w16 + O_PXQK, o}; o += 1024;
        W.j[2]  = {pc_v_w,   w16 + O_PCV,  o}; o += 512;
        W.j[3]  = {px_v_w,   w16 + O_PXV,  o}; o += 512;
        W.j[4]  = {p1_proj_w, w16 + O_P1P, o}; o += 512;
        W.j[5]  = {p2_proj_w, w16 + O_P2P, o}; o += 512;
        W.j[6]  = {p1_w1,    w16 + O_P1W1, o}; o += 2048;
        W.j[7]  = {p1_w3,    w16 + O_P1W3, o}; o += 2048;
        W.j[8]  = {p2_w1,    w16 + O_P2W1, o}; o += 2048;
        W.j[9]  = {p2_w3,    w16 + O_P2W3, o}; o += 2048;
        W.j[10] = {p1_w2,    w16 + O_P1W2, o}; o += 2048;
        W.j[11] = {p2_w2,    w16 + O_P2W2, o}; o += 2048;
        prologue<<<CVT_BLKS + L_X + S_C, 256>>>(W, x, xln16, L_X, c, cln16);
    }

    // 2) QKV GEMMs; qk fp16 out, V fp16 dim-major (one batched launch)
    {
        GJobs J; J.n = 4;
        int o = 0;
        J.j[0] = {cln16, w16 + O_PCQK, nullptr, nullptr, qk16c, 2 * D, D, o, 2, 0};  o += nct(S_C, 2 * D);
        J.j[1] = {cln16, w16 + O_PCV,  pc_v_b,  nullptr, v16t,  D,     D, o, 1, 0};  o += nct(S_C, D);
        J.j[2] = {xln16, w16 + O_PXQK, nullptr, nullptr, qk16x, 2 * D, D, o, 2, 0};  o += nct(L_X, 2 * D);
        J.j[3] = {xln16, w16 + O_PXV,  px_v_b,  nullptr, v16t,  D,     D, o, 1, S_C}; o += nct(L_X, D);
        mma_gemm_mj<<<o, 128, MMG_SMEM>>>(J);
    }
    qk_finish_all<<<TT * H / 8, 256>>>(qk16c, qk16x, pc_qn, pc_kn, px_qn, px_kn, freqs, q16, k16);

    // 3) causal attention -> y fp16
    attn_tc<<<dim3(32, H), 128, ATN_SMEM>>>(q16, k16, v16t, y16);

    // 4) output projections (batched)
    const __half* yx16 = y16 + (size_t)S_C * D;
    {
        GJobs J; J.n = 2;
        int o = 0;
        J.j[0] = {yx16, w16 + O_P1P, p1_proj_b, x, x1x, D, D, o, 0, 0}; o += nct(L_X, D);
        J.j[1] = {y16,  w16 + O_P2P, p2_proj_b, c, x1c, D, D, o, 0, 0}; o += nct(S_C, D);
        J.j[2] = J.j[0]; J.j[3] = J.j[0];
        mma_gemm_mj<<<o, 128, MMG_SMEM>>>(J);
    }
    ln2_kernel<<<L_X + S_C, 256>>>(x1x, h16x, L_X, x1c, h16c);

    // 5) w1/w3 (one batched launch, R12 shape) -> fp16 outputs
    {
        GJobs J; J.n = 4;
        int o = 0;
        J.j[0] = {h16x, w16 + O_P1W1, p1_b1, nullptr, t16x1, FF, D, o, 2, 0}; o += nct(L_X, FF);
        J.j[1] = {h16x, w16 + O_P1W3, p1_b3, nullptr, t16x3, FF, D, o, 2, 0}; o += nct(L_X, FF);
        J.j[2] = {h16c, w16 + O_P2W1, p2_b1, nullptr, t16c1, FF, D, o, 2, 0}; o += nct(S_C, FF);
        J.j[3] = {h16c, w16 + O_P2W3, p2_b3, nullptr, t16c3, FF, D, o, 2, 0}; o += nct(S_C, FF);
        mma_gemm_mj<<<o, 128, MMG_SMEM>>>(J);
    }
    silu_all<<<(TT * FF / 2 + 255) / 256, 256>>>(t16x1, t16x3, g16x, L_X * FF, t16c1, t16c3, g16c, S_C * FF);

    // 6) w2 (batched)
    {
        GJobs J; J.n = 2;
        int o = 0;
        J.j[0] = {g16x, w16 + O_P1W2, p1_b2, x1x, out,                   D, FF, o, 0, 0}; o += nct(L_X, D);
        J.j[1] = {g16c, w16 + O_P2W2, p2_b2, x1c, out + (size_t)L_X * D, D, FF, o, 0, 0}; o += nct(S_C, D);
        J.j[2] = J.j[0]; J.j[3] = J.j[0];
        mma_gemm_mj<<<o, 128, MMG_SMEM>>>(J);
    }
}

// round 16
// speedup vs baseline: 1.1632x; 1.0050x over previous
#include <cuda_runtime.h>
#include <cuda_fp16.h>
#include <cstdint>
#include <math.h>

// ---------------- problem constants ----------------
#define L_X   1536
#define S_C   512
#define TT    2048          // L_X + S_C
#define D     1024
#define H     16
#define HD    64
#define FF    4096

// ---------------- scratch (device globals; no cudaMalloc allowed) ----------
__device__ float g_x1x[L_X * D];
__device__ float g_x1c[S_C * D];

// fp16 buffers
__device__ __half g_w16  [33554432];
__device__ __half g_qk16x[L_X * 2 * D];
__device__ __half g_qk16c[S_C * 2 * D];
__device__ __half g_cln16[S_C * D];
__device__ __half g_xln16[L_X * D];
__device__ __half g_q16  [H * TT * HD];
__device__ __half g_k16  [H * TT * HD];
__device__ __half g_v16t [H * HD * TT];
__device__ __half g_y16  [TT * D];
__device__ __half g_h16x [L_X * D];
__device__ __half g_h16c [S_C * D];
__device__ __half g_t16x1[L_X * FF];
__device__ __half g_t16x3[L_X * FF];
__device__ __half g_t16c1[S_C * FF];
__device__ __half g_t16c3[S_C * FF];
__device__ __half g_g16x [L_X * FF];
__device__ __half g_g16c [S_C * FF];

// arena offsets (halves)
#define O_PCQK 0
#define O_PXQK 2097152
#define O_PCV  4194304
#define O_PXV  5242880
#define O_P1P  6291456
#define O_P2P  7340032
#define O_P1W1 8388608
#define O_P1W3 12582912
#define O_P2W1 16777216
#define O_P2W3 20971520
#define O_P1W2 25165824
#define O_P2W2 29360128

// ---------------- utils ----------------
__device__ __forceinline__ float warpSum(float v) {
    #pragma unroll
    for (int o = 16; o > 0; o >>= 1) v += __shfl_xor_sync(0xffffffffu, v, o);
    return v;
}
__device__ __forceinline__ float ex2f(float x) {
    float y;
    asm("ex2.approx.f32 %0, %1;" : "=f"(y) : "f"(x));
    return y;
}
__device__ __forceinline__ void mma_f16(float* d, const uint32_t* a, const uint32_t* b) {
    asm volatile(
        "mma.sync.aligned.m16n8k16.row.col.f32.f16.f16.f32 "
        "{%0,%1,%2,%3}, {%4,%5,%6,%7}, {%8,%9}, {%0,%1,%2,%3};"
        : "+f"(d[0]), "+f"(d[1]), "+f"(d[2]), "+f"(d[3])
        : "r"(a[0]), "r"(a[1]), "r"(a[2]), "r"(a[3]), "r"(b[0]), "r"(b[1]));
}
__device__ __forceinline__ void ldsm_x4(uint32_t* r, uint32_t addr) {
    asm volatile("ldmatrix.sync.aligned.m8n8.x4.shared.b16 {%0,%1,%2,%3}, [%4];"
        : "=r"(r[0]), "=r"(r[1]), "=r"(r[2]), "=r"(r[3]) : "r"(addr));
}
__device__ __forceinline__ uint32_t smem_u32(const void* p) {
    uint32_t a;
    asm("{ .reg .u64 t; cvta.to.shared.u64 t, %1; cvt.u32.u64 %0, t; }" : "=r"(a) : "l"(p));
    return a;
}
__device__ __forceinline__ void cp_async16(uint32_t saddr, const void* gaddr) {
    asm volatile("cp.async.cg.shared.global [%0], [%1], 16;" :: "r"(saddr), "l"(gaddr));
}
#define CP_COMMIT() asm volatile("cp.async.commit_group;" ::: "memory")
#define CP_WAIT0()  asm volatile("cp.async.wait_group 0;" ::: "memory")
#define CP_WAIT1()  asm volatile("cp.async.wait_group 1;" ::: "memory")

// ---------------- fused prologue: weight cvt (12 jobs) + LayerNorm ------
struct WJob { const float* src; __half* dst; int off; };
struct WJobs { WJob j[12]; };

#define CVT_BLKS 16384

__global__ __launch_bounds__(256)
void prologue(WJobs J,
              const float* __restrict__ lx, __half* __restrict__ lox, int rows0,
              const float* __restrict__ lc, __half* __restrict__ loc) {
    if ((int)blockIdx.x < CVT_BLKS) {
        int ji = 0;
        #pragma unroll
        for (int t = 1; t < 12; t++) if ((int)blockIdx.x >= J.j[t].off) ji = t;
        size_t idx = ((size_t)(blockIdx.x - J.j[ji].off) * 256 + threadIdx.x) * 8;
        const float4* s = (const float4*)(J.j[ji].src + idx);
        float4 v0 = s[0], v1 = s[1];
        __half2* d = (__half2*)(J.j[ji].dst + idx);
        d[0] = __floats2half2_rn(v0.x, v0.y);
        d[1] = __floats2half2_rn(v0.z, v0.w);
        d[2] = __floats2half2_rn(v1.x, v1.y);
        d[3] = __floats2half2_rn(v1.z, v1.w);
        return;
    }
    int row = blockIdx.x - CVT_BLKS;
    const float* x;
    __half* o;
    if (row < rows0) { x = lx + (size_t)row * D; o = lox + (size_t)row * D; }
    else             { x = lc + (size_t)(row - rows0) * D; o = loc + (size_t)(row - rows0) * D; }
    float4 v = *(const float4*)(x + threadIdx.x * 4);
    float s = v.x + v.y + v.z + v.w;
    float ss = v.x * v.x + v.y * v.y + v.z * v.z + v.w * v.w;
    __shared__ float shs[8], shss[8];
    float ws = warpSum(s), wss = warpSum(ss);
    int w = threadIdx.x >> 5;
    if ((threadIdx.x & 31) == 0) { shs[w] = ws; shss[w] = wss; }
    __syncthreads();
    float ts = 0.f, tss = 0.f;
    #pragma unroll
    for (int i = 0; i < 8; i++) { ts += shs[i]; tss += shss[i]; }
    float mean = ts * (1.0f / D);
    float var  = tss * (1.0f / D) - mean * mean;
    float inv  = rsqrtf(var + 1e-6f);
    __half2* o2 = (__half2*)(o + threadIdx.x * 4);
    o2[0] = __floats2half2_rn((v.x - mean) * inv, (v.y - mean) * inv);
    o2[1] = __floats2half2_rn((v.z - mean) * inv, (v.w - mean) * inv);
}

// ---------------- LayerNorm pair -> fp16 (row cached in registers) -----
__global__ __launch_bounds__(256)
void ln2_kernel(const float* __restrict__ in0, __half* __restrict__ out0,
                int rows0,
                const float* __restrict__ in1, __half* __restrict__ out1) {
    int row = blockIdx.x;
    const float* x;
    __half* o;
    if (row < rows0) { x = in0 + (size_t)row * D; o = out0 + (size_t)row * D; }
    else             { x = in1 + (size_t)(row - rows0) * D; o = out1 + (size_t)(row - rows0) * D; }
    float4 v = *(const float4*)(x + threadIdx.x * 4);
    float s = v.x + v.y + v.z + v.w;
    float ss = v.x * v.x + v.y * v.y + v.z * v.z + v.w * v.w;
    __shared__ float shs[8], shss[8];
    float ws = warpSum(s), wss = warpSum(ss);
    int w = threadIdx.x >> 5;
    if ((threadIdx.x & 31) == 0) { shs[w] = ws; shss[w] = wss; }
    __syncthreads();
    float ts = 0.f, tss = 0.f;
    #pragma unroll
    for (int i = 0; i < 8; i++) { ts += shs[i]; tss += shss[i]; }
    float mean = ts * (1.0f / D);
    float var  = tss * (1.0f / D) - mean * mean;
    float inv  = rsqrtf(var + 1e-6f);
    __half2* o2 = (__half2*)(o + threadIdx.x * 4);
    o2[0] = __floats2half2_rn((v.x - mean) * inv, (v.y - mean) * inv);
    o2[1] = __floats2half2_rn((v.z - mean) * inv, (v.w - mean) * inv);
}

// ======================================================================
// Multi-job fp16 GEMM (m16n8k16), K-chunk 32, 3-stage cp.async, ldmatrix.
// (R12 configuration: 61.4KB smem -> 3 CTAs/SM.) UNCHANGED.
// ======================================================================
struct GJob {
    const __half* A; const __half* B; const float* bias; const float* resid;
    void* C; int N, K, off, mode, t_off;
};
struct GJobs { GJob j[4]; int n; };

#define HST 20
#define HBUF (128 * HST)
#define MMG_SMEM (3 * 2 * HBUF * 4)

__global__ __launch_bounds__(128)
void mma_gemm_mj(GJobs jobs) {
    int ji = 0;
    if (jobs.n > 1 && (int)blockIdx.x >= jobs.j[1].off) ji = 1;
    if (jobs.n > 2 && (int)blockIdx.x >= jobs.j[2].off) ji = 2;
    if (jobs.n > 3 && (int)blockIdx.x >= jobs.j[3].off) ji = 3;
    const __half* A = jobs.j[ji].A;
    const __half* B = jobs.j[ji].B;
    const float* bias = jobs.j[ji].bias;
    const float* resid = jobs.j[ji].resid;
    void* C = jobs.j[ji].C;
    int N = jobs.j[ji].N, K = jobs.j[ji].K;
    int mode = jobs.j[ji].mode, t_off = jobs.j[ji].t_off;
    int lid0 = blockIdx.x - jobs.j[ji].off;
    int nbx = N >> 7;
    int by = lid0 / nbx, bx = lid0 - by * nbx;
    int m0 = by * 128, n0 = bx * 128;

    extern __shared__ uint32_t smw[];
    uint32_t sbase = smem_u32(smw);
    int tid = threadIdx.x;
    int wid = tid >> 5, lane = tid & 31;
    int gid = lane >> 2, tig = lane & 3;
    int warp_m = wid >> 1, warp_n = wid & 1;

    float acc[4][8][4];
    #pragma unroll
    for (int mt = 0; mt < 4; mt++)
        #pragma unroll
        for (int nt = 0; nt < 8; nt++)
            #pragma unroll
            for (int e = 0; e < 4; e++) acc[mt][nt][e] = 0.f;

    const int nchunk = K >> 5;
    int lrow = tid >> 2;
    int lblk = tid & 3;

    int tileid = lane >> 3;
    uint32_t aoff = (uint32_t)(warp_m * 64 + (tileid & 1) * 8 + (lane & 7)) * 80
                    + (uint32_t)(tileid >> 1) * 16;
    uint32_t boff = (uint32_t)(warp_n * 64 + (tileid >> 1) * 8 + (lane & 7)) * 80
                    + (uint32_t)(tileid & 1) * 16;

    #pragma unroll
    for (int pc = 0; pc < 2; pc++) {
        const __half* Ap = A + (size_t)m0 * K + pc * 32 + lblk * 8;
        const __half* Bp = B + (size_t)n0 * K + pc * 32 + lblk * 8;
        uint32_t sA = sbase + pc * 2 * HBUF * 4;
        uint32_t sB = sA + HBUF * 4;
        #pragma unroll
        for (int l = 0; l < 4; l++) {
            int r = lrow + l * 32;
            uint32_t so = (r * HST + lblk * 4) * 4;
            cp_async16(sA + so, Ap + (size_t)r * K);
            cp_async16(sB + so, Bp + (size_t)r * K);
        }
        CP_COMMIT();
    }

    int st = 0;
    for (int i = 0; i < nchunk; i++) {
        CP_WAIT1();
        __syncthreads();
        if (i + 2 < nchunk) {
            int ps = st + 2; if (ps >= 3) ps -= 3;
            const __half* Ap = A + (size_t)m0 * K + (i + 2) * 32 + lblk * 8;
            const __half* Bp = B + (size_t)n0 * K + (i + 2) * 32 + lblk * 8;
            uint32_t sA = sbase + ps * 2 * HBUF * 4;
            uint32_t sB = sA + HBUF * 4;
            #pragma unroll
            for (int l = 0; l < 4; l++) {
                int r = lrow + l * 32;
                uint32_t so = (r * HST + lblk * 4) * 4;
                cp_async16(sA + so, Ap + (size_t)r * K);
                cp_async16(sB + so, Bp + (size_t)r * K);
            }
        }
        CP_COMMIT();
        uint32_t stA = sbase + st * 2 * HBUF * 4;
        uint32_t stB = stA + HBUF * 4;
        #pragma unroll
        for (int s = 0; s < 2; s++) {
            uint32_t kbyte = s * 32;
            uint32_t af[4][4], bf[4][4];
            #pragma unroll
            for (int mt = 0; mt < 4; mt++)
                ldsm_x4(af[mt], stA + aoff + (uint32_t)mt * (16 * 80) + kbyte);
            #pragma unroll
            for (int ntp = 0; ntp < 4; ntp++)
                ldsm_x4(bf[ntp], stB + boff + (uint32_t)ntp * (16 * 80) + kbyte);
            #pragma unroll
            for (int mt = 0; mt < 4; mt++)
                #pragma unroll
                for (int ntp = 0; ntp < 4; ntp++) {
                    mma_f16(acc[mt][ntp * 2 + 0], af[mt], &bf[ntp][0]);
                    mma_f16(acc[mt][ntp * 2 + 1], af[mt], &bf[ntp][2]);
                }
        }
        st++; if (st >= 3) st = 0;
    }

    #pragma unroll
    for (int mt = 0; mt < 4; mt++) {
        #pragma unroll
        for (int nt = 0; nt < 8; nt++) {
            int row = m0 + warp_m * 64 + mt * 16 + gid;
            int col = n0 + warp_n * 64 + nt * 8 + tig * 2;
            #pragma unroll
            for (int half = 0; half < 2; half++) {
                int r = row + half * 8;
                float2 v = make_float2(acc[mt][nt][half * 2], acc[mt][nt][half * 2 + 1]);
                if (bias) {
                    float2 bv2 = *(const float2*)(bias + col);
                    v.x += bv2.x; v.y += bv2.y;
                }
                if (mode == 0) {
                    float* Cf = (float*)C;
                    size_t off = (size_t)r * N + col;
                    if (resid) {
                        float2 rv = *(const float2*)(resid + off);
                        v.x += rv.x; v.y += rv.y;
                    }
                    *(float2*)(Cf + off) = v;
                } else if (mode == 1) {
                    __half* Ch = (__half*)C;
                    int hh = col >> 6, dd = col & 63;
                    Ch[((size_t)hh * HD + dd) * TT + t_off + r]     = __float2half_rn(v.x);
                    Ch[((size_t)hh * HD + dd + 1) * TT + t_off + r] = __float2half_rn(v.y);
                } else {
                    __half* Ch = (__half*)C;
                    *(__half2*)(Ch + (size_t)r * N + col) = __floats2half2_rn(v.x, v.y);
                }
            }
        }
    }
}

// ---------------- qk finish: warp per (t,h), lane owns RoPE pair --------
__global__ __launch_bounds__(256)
void qk_finish_all(const __half* __restrict__ qkc, const __half* __restrict__ qkx,
                   const float* __restrict__ cqn, const float* __restrict__ ckn,
                   const float* __restrict__ xqn, const float* __restrict__ xkn,
                   const float* __restrict__ freqs,
                   __half* __restrict__ Q, __half* __restrict__ Ko) {
    int gidx = blockIdx.x * 8 + (threadIdx.x >> 5);
    int lane = threadIdx.x & 31;
    int t = gidx >> 4;
    int h = gidx & 15;
    const __half* qk; const float* qn; const float* kn; int row;
    if (t < S_C) { qk = qkc; qn = cqn; kn = ckn; row = t; }
    else         { qk = qkx; qn = xqn; kn = xkn; row = t - S_C; }
    size_t base = (size_t)row * (2 * D) + h * HD + lane * 2;
    float2 qv = __half22float2(*(const __half2*)(qk + base));
    float2 kv = __half22float2(*(const __half2*)(qk + base + D));
    float sq = qv.x * qv.x + qv.y * qv.y;
    float sk = kv.x * kv.x + kv.y * kv.y;
    #pragma unroll
    for (int o = 16; o > 0; o >>= 1) {
        sq += __shfl_xor_sync(0xffffffffu, sq, o);
        sk += __shfl_xor_sync(0xffffffffu, sk, o);
    }
    float rq = rsqrtf(sq * (1.0f / HD) + 1e-6f);
    float rk = rsqrtf(sk * (1.0f / HD) + 1e-6f);
    float2 qw = *(const float2*)(qn + lane * 2);
    float2 kw = *(const float2*)(kn + lane * 2);
    float q0 = qv.x * rq * qw.x, q1 = qv.y * rq * qw.y;
    float k0 = kv.x * rk * kw.x, k1 = kv.y * rk * kw.y;
    float2 f = *(const float2*)(freqs + ((size_t)t * 32 + lane) * 2);
    float cs = f.x, sn = f.y;
    const float QSC = 0.125f * 1.4426950408889634f;
    float oq0 = (q0 * cs - q1 * sn) * QSC;
    float oq1 = (q0 * sn + q1 * cs) * QSC;
    float ok0 = k0 * cs - k1 * sn;
    float ok1 = k0 * sn + k1 * cs;
    size_t off = ((size_t)h * TT + t) * HD + lane * 2;
    *(__half2*)(Q + off)  = __floats2half2_rn(oq0, oq1);
    *(__half2*)(Ko + off) = __floats2half2_rn(ok0, ok1);
}

// ======================================================================
// fp16 flash attention: 128-row q-tiles, 8 warps, ldmatrix fragments.
// smem words: Qs[128x36] | Ks0[64x36] | Ks1 | Vt0 | Vt1 | Pw[128x36]
// ======================================================================
#define AHS 72
#define AWS 36
#define ATN_SMEM (512 * AWS * 4)     // 73728 bytes

__global__ __launch_bounds__(256)
void attn_tc(const __half* __restrict__ Q, const __half* __restrict__ K,
             const __half* __restrict__ V, __half* __restrict__ Y) {
    extern __shared__ uint32_t smw[];
    uint32_t sbase = smem_u32(smw);
    int tid = threadIdx.x, wid = tid >> 5, lane = tid & 31;
    int gid = lane >> 2, tig = lane & 3;
    int bxr = 15 - blockIdx.x;               // heavy tiles first
    int h = blockIdx.y;
    int q0 = bxr * 128;
    const __half* Qh = Q + (size_t)h * TT * HD;
    const __half* Kh = K + (size_t)h * TT * HD;
    const __half* Vh = V + (size_t)h * HD * TT;

    const uint32_t* QsW = smw;
    uint32_t* PwW = smw + 384 * AWS;

    int lrowq = tid >> 1;              // 0..127 (Q rows)
    int lblkq = tid & 1;
    int lrowk = tid >> 2;              // 0..63 (K/V rows)
    int lblkk = tid & 3;

    int tileid = lane >> 3;
    uint32_t poff = (uint32_t)(wid * 16 + (tileid & 1) * 8 + (lane & 7)) * (AHS * 2)
                    + (uint32_t)(tileid >> 1) * 16;
    uint32_t boff = (uint32_t)((tileid >> 1) * 8 + (lane & 7)) * (AHS * 2)
                    + (uint32_t)(tileid & 1) * 16;

    // prologue: Q tile (128 rows) + K/V tile 0 (64 rows each)
    {
        uint32_t qb = sbase;
        uint32_t kb = sbase + (128 * AWS) * 4;
        uint32_t vb = sbase + (256 * AWS) * 4;
        #pragma unroll
        for (int j = 0; j < 4; j++) {
            uint32_t so = (lrowq * AHS + lblkq * 32 + j * 8) * 2;
            cp_async16(qb + so, Qh + (size_t)(q0 + lrowq) * HD + lblkq * 32 + j * 8);
        }
        #pragma unroll
        for (int j = 0; j < 2; j++) {
            uint32_t so = (lrowk * AHS + lblkk * 8 + j * 32) * 2;
            cp_async16(kb + so, Kh + (size_t)lrowk * HD + lblkk * 8 + j * 32);
            cp_async16(vb + so, Vh + (size_t)lrowk * TT + lblkk * 8 + j * 32);
        }
        CP_COMMIT();
    }
    CP_WAIT0();
    __syncthreads();

    uint32_t qf[4][4];
    int qrow = wid * 16 + gid;
    #pragma unroll
    for (int ks = 0; ks < 4; ks++) {
        qf[ks][0] = QsW[qrow * AWS + ks * 8 + tig];
        qf[ks][1] = QsW[(qrow + 8) * AWS + ks * 8 + tig];
        qf[ks][2] = QsW[qrow * AWS + ks * 8 + tig + 4];
        qf[ks][3] = QsW[(qrow + 8) * AWS + ks * 8 + tig + 4];
    }
    __syncwarp();

    float ofr[8][4];
    #pragma unroll
    for (int ot = 0; ot < 8; ot++)
        #pragma unroll
        for (int e = 0; e < 4; e++) ofr[ot][e] = 0.f;
    float m0r = -INFINITY, m1r = -INFINITY, l0r = 0.f, l1r = 0.f;

    int ntile = 2 * bxr + 2;
    for (int kt = 0; kt < ntile; kt++) {
        int k0g = kt * 64;
        int buf = kt & 1;
        uint32_t kbase = sbase + ((128 + buf * 64) * AWS) * 4;
        uint32_t vbase = sbase + ((256 + buf * 64) * AWS) * 4;
        uint32_t pbase = sbase + (384 * AWS) * 4;
        if (kt > 0) { CP_WAIT0(); __syncthreads(); }
        float sacc[8][4];
        #pragma unroll
        for (int nt = 0; nt < 8; nt++)
            #pragma unroll
            for (int e = 0; e < 4; e++) sacc[nt][e] = 0.f;
        #pragma unroll
        for (int ks = 0; ks < 4; ks++) {
            uint32_t bk[4][4];
            #pragma unroll
            for (int kp = 0; kp < 4; kp++)
                ldsm_x4(bk[kp], kbase + boff + (uint32_t)kp * (16 * AHS * 2) + ks * 32);
            #pragma unroll
            for (int kp = 0; kp < 4; kp++) {
                mma_f16(sacc[kp * 2 + 0], qf[ks], &bk[kp][0]);
                mma_f16(sacc[kp * 2 + 1], qf[ks], &bk[kp][2]);
            }
        }
        if (kt + 1 < ntile) {
            uint32_t kb = sbase + ((128 + (buf ^ 1) * 64) * AWS) * 4;
            uint32_t vb = sbase + ((256 + (buf ^ 1) * 64) * AWS) * 4;
            const __half* Kp = Kh + (size_t)(k0g + 64) * HD;
            const __half* Vp = Vh + k0g + 64;
            #pragma unroll
            for (int j = 0; j < 2; j++) {
                uint32_t so = (lrowk * AHS + lblkk * 8 + j * 32) * 2;
                cp_async16(kb + so, Kp + (size_t)lrowk * HD + lblkk * 8 + j * 32);
                cp_async16(vb + so, Vp + (size_t)lrowk * TT + lblkk * 8 + j * 32);
            }
        }
        CP_COMMIT();
        if (kt >= ntile - 2) {
            int r0 = q0 + wid * 16 + gid;
            #pragma unroll
            for (int nt = 0; nt < 8; nt++) {
                int c0 = k0g + nt * 8 + tig * 2;
                if (c0 > r0)     sacc[nt][0] = -INFINITY;
                if (c0 + 1 > r0) sacc[nt][1] = -INFINITY;
                if (c0 > r0 + 8)     sacc[nt][2] = -INFINITY;
                if (c0 + 1 > r0 + 8) sacc[nt][3] = -INFINITY;
            }
        }
        float tm0 = -INFINITY, tm1 = -INFINITY;
        #pragma unroll
        for (int nt = 0; nt < 8; nt++) {
            tm0 = fmaxf(tm0, fmaxf(sacc[nt][0], sacc[nt][1]));
            tm1 = fmaxf(tm1, fmaxf(sacc[nt][2], sacc[nt][3]));
        }
        #pragma unroll
        for (int o = 1; o < 4; o <<= 1) {
            tm0 = fmaxf(tm0, __shfl_xor_sync(0xffffffffu, tm0, o));
            tm1 = fmaxf(tm1, __shfl_xor_sync(0xffffffffu, tm1, o));
        }
        float nm0 = fmaxf(m0r, tm0), nm1 = fmaxf(m1r, tm1);
        float c0 = ex2f(m0r - nm0), c1 = ex2f(m1r - nm1);
        m0r = nm0; m1r = nm1;
        float ps0 = 0.f, ps1 = 0.f;
        int row0 = wid * 16 + gid, row1 = row0 + 8;
        #pragma unroll
        for (int nt = 0; nt < 8; nt++) {
            float p00 = ex2f(sacc[nt][0] - nm0);
            float p01 = ex2f(sacc[nt][1] - nm0);
            float p10 = ex2f(sacc[nt][2] - nm1);
            float p11 = ex2f(sacc[nt][3] - nm1);
            ps0 += p00 + p01; ps1 += p10 + p11;
            __half2 h0 = __floats2half2_rn(p00, p01);
            __half2 h1 = __floats2half2_rn(p10, p11);
            PwW[row0 * AWS + nt * 4 + tig] = *(uint32_t*)&h0;
            PwW[row1 * AWS + nt * 4 + tig] = *(uint32_t*)&h1;
        }
        #pragma unroll
        for (int o = 1; o < 4; o <<= 1) {
            ps0 += __shfl_xor_sync(0xffffffffu, ps0, o);
            ps1 += __shfl_xor_sync(0xffffffffu, ps1, o);
        }
        l0r = l0r * c0 + ps0;
        l1r = l1r * c1 + ps1;
        #pragma unroll
        for (int ot = 0; ot < 8; ot++) {
            ofr[ot][0] *= c0; ofr[ot][1] *= c0;
            ofr[ot][2] *= c1; ofr[ot][3] *= c1;
        }
        __syncwarp();
        #pragma unroll
        for (int ks = 0; ks < 4; ks++) {
            uint32_t af[4];
            ldsm_x4(af, pbase + poff + ks * 32);
            uint32_t bv[4][4];
            #pragma unroll
            for (int vp = 0; vp < 4; vp++)
                ldsm_x4(bv[vp], vbase + boff + (uint32_t)vp * (16 * AHS * 2) + ks * 32);
            #pragma unroll
            for (int vp = 0; vp < 4; vp++) {
                mma_f16(ofr[vp * 2 + 0], af, &bv[vp][0]);
                mma_f16(ofr[vp * 2 + 1], af, &bv[vp][2]);
            }
        }
        __syncwarp();
    }
    float i0 = 1.0f / l0r, i1 = 1.0f / l1r;
    int t0 = q0 + wid * 16 + gid, t1 = t0 + 8;
    #pragma unroll
    for (int ot = 0; ot < 8; ot++) {
        int col = h * HD + ot * 8 + tig * 2;
        *(__half2*)(Y + (size_t)t0 * D + col) = __floats2half2_rn(ofr[ot][0] * i0, ofr[ot][1] * i0);
        *(__half2*)(Y + (size_t)t1 * D + col) = __floats2half2_rn(ofr[ot][2] * i1, ofr[ot][3] * i1);
    }
}

// ---------------- SiLU gate fp16 -> fp16 (fast sigmoid) ----------------
__global__ __launch_bounds__(256)
void silu_all(const __half* __restrict__ a0, const __half* __restrict__ b0,
              __half* __restrict__ g0, int n0,
              const __half* __restrict__ a1, const __half* __restrict__ b1,
              __half* __restrict__ g1, int n1) {
    const float L2E = 1.4426950408889634f;
    int i = blockIdx.x * 256 + threadIdx.x;
    int h0 = n0 >> 1;
    if (i < h0) {
        __half2 av = ((const __half2*)a0)[i];
        __half2 bv = ((const __half2*)b0)[i];
        float x0 = __half2float(__low2half(av)), x1 = __half2float(__high2half(av));
        float s0 = x0 / (1.0f + ex2f(-x0 * L2E)) * __half2float(__low2half(bv));
        float s1 = x1 / (1.0f + ex2f(-x1 * L2E)) * __half2float(__high2half(bv));
        ((__half2*)g0)[i] = __floats2half2_rn(s0, s1);
    } else if (i < h0 + (n1 >> 1)) {
        int j = i - h0;
        __half2 av = ((const __half2*)a1)[j];
        __half2 bv = ((const __half2*)b1)[j];
        float x0 = __half2float(__low2half(av)), x1 = __half2float(__high2half(av));
        float s0 = x0 / (1.0f + ex2f(-x0 * L2E)) * __half2float(__low2half(bv));
        float s1 = x1 / (1.0f + ex2f(-x1 * L2E)) * __half2float(__high2half(bv));
        ((__half2*)g1)[j] = __floats2half2_rn(s0, s1);
    }
}

// ---------------- host launcher ----------------
static inline int nct(int M, int N) { return (M / 128) * (N / 128); }

extern "C" void kernel_launch(void* const* d_in, const int* in_sizes, int n_in,
                              void* d_out, int out_size) {
    const float* x        = (const float*)d_in[0];
    const float* c        = (const float*)d_in[1];
    const float* freqs    = (const float*)d_in[2];
    const float* px_qk_w  = (const float*)d_in[3];
    const float* px_qn    = (const float*)d_in[4];
    const float* px_kn    = (const float*)d_in[5];
    const float* px_v_w   = (const float*)d_in[6];
    const float* px_v_b   = (const float*)d_in[7];
    const float* pc_qk_w  = (const float*)d_in[8];
    const float* pc_qn    = (const float*)d_in[9];
    const float* pc_kn    = (const float*)d_in[10];
    const float* pc_v_w   = (const float*)d_in[11];
    const float* pc_v_b   = (const float*)d_in[12];
    const float* p1_proj_w = (const float*)d_in[13];
    const float* p1_proj_b = (const float*)d_in[14];
    const float* p1_w1    = (const float*)d_in[15];
    const float* p1_b1    = (const float*)d_in[16];
    const float* p1_w3    = (const float*)d_in[17];
    const float* p1_b3    = (const float*)d_in[18];
    const float* p1_w2    = (const float*)d_in[19];
    const float* p1_b2    = (const float*)d_in[20];
    const float* p2_proj_w = (const float*)d_in[21];
    const float* p2_proj_b = (const float*)d_in[22];
    const float* p2_w1    = (const float*)d_in[23];
    const float* p2_b1    = (const float*)d_in[24];
    const float* p2_w3    = (const float*)d_in[25];
    const float* p2_b3    = (const float*)d_in[26];
    const float* p2_w2    = (const float*)d_in[27];
    const float* p2_b2    = (const float*)d_in[28];
    float* out = (float*)d_out;

    float *x1x, *x1c;
    __half *w16, *qk16x, *qk16c, *cln16, *xln16, *q16, *k16, *v16t, *y16;
    __half *h16x, *h16c, *t16x1, *t16x3, *t16c1, *t16c3, *g16x, *g16c;
    cudaGetSymbolAddress((void**)&x1x, g_x1x);
    cudaGetSymbolAddress((void**)&x1c, g_x1c);
    cudaGetSymbolAddress((void**)&w16,   g_w16);
    cudaGetSymbolAddress((void**)&qk16x, g_qk16x);
    cudaGetSymbolAddress((void**)&qk16c, g_qk16c);
    cudaGetSymbolAddress((void**)&cln16, g_cln16);
    cudaGetSymbolAddress((void**)&xln16, g_xln16);
    cudaGetSymbolAddress((void**)&q16,   g_q16);
    cudaGetSymbolAddress((void**)&k16,   g_k16);
    cudaGetSymbolAddress((void**)&v16t,  g_v16t);
    cudaGetSymbolAddress((void**)&y16,   g_y16);
    cudaGetSymbolAddress((void**)&h16x,  g_h16x);
    cudaGetSymbolAddress((void**)&h16c,  g_h16c);
    cudaGetSymbolAddress((void**)&t16x1, g_t16x1);
    cudaGetSymbolAddress((void**)&t16x3, g_t16x3);
    cudaGetSymbolAddress((void**)&t16c1, g_t16c1);
    cudaGetSymbolAddress((void**)&t16c3, g_t16c3);
    cudaGetSymbolAddress((void**)&g16x,  g_g16x);
    cudaGetSymbolAddress((void**)&g16c,  g_g16c);

    cudaFuncSetAttribute(attn_tc, cudaFuncAttributeMaxDynamicSharedMemorySize, ATN_SMEM);
    cudaFuncSetAttribute(mma_gemm_mj, cudaFuncAttributeMaxDynamicSharedMemorySize, MMG_SMEM);

    // 0) fused prologue: weight cvt + LayerNorm both streams
    {
        WJobs W;
        int o = 0;
        W.j[0]  = {pc_qk_w,  w16 + O_PCQK, o}; o += 1024;
        W.j[1]  = {px_qk_w,  w16 + O_PXQK, o}; o += 1024;
        W.j[2]  = {pc_v_w,   w16 + O_PCV,  o}; o += 512;
        W.j[3]  = {px_v_w,   w16 + O_PXV,  o}; o += 512;
        W.j[4]  = {p1_proj_w, w16 + O_P1P, o}; o += 512;
        W.j[5]  = {p2_proj_w, w16 + O_P2P, o}; o += 512;
        W.j[6]  = {p1_w1,    w16 + O_P1W1, o}; o += 2048;
        W.j[7]  = {p1_w3,    w16 + O_P1W3, o}; o += 2048;
        W.j[8]  = {p2_w1,    w16 + O_P2W1, o}; o += 2048;
        W.j[9]  = {p2_w3,    w16 + O_P2W3, o}; o += 2048;
        W.j[10] = {p1_w2,    w16 + O_P1W2, o}; o += 2048;
        W.j[11] = {p2_w2,    w16 + O_P2W2, o}; o += 2048;
        prologue<<<CVT_BLKS + L_X + S_C, 256>>>(W, x, xln16, L_X, c, cln16);
    }

    // 2) QKV GEMMs; qk fp16 out, V fp16 dim-major (one batched launch)
    {
        GJobs J; J.n = 4;
        int o = 0;
        J.j[0] = {cln16, w16 + O_PCQK, nullptr, nullptr, qk16c, 2 * D, D, o, 2, 0};  o += nct(S_C, 2 * D);
        J.j[1] = {cln16, w16 + O_PCV,  pc_v_b,  nullptr, v16t,  D,     D, o, 1, 0};  o += nct(S_C, D);
        J.j[2] = {xln16, w16 + O_PXQK, nullptr, nullptr, qk16x, 2 * D, D, o, 2, 0};  o += nct(L_X, 2 * D);
        J.j[3] = {xln16, w16 + O_PXV,  px_v_b,  nullptr, v16t,  D,     D, o, 1, S_C}; o += nct(L_X, D);
        mma_gemm_mj<<<o, 128, MMG_SMEM>>>(J);
    }
    qk_finish_all<<<TT * H / 8, 256>>>(qk16c, qk16x, pc_qn, pc_kn, px_qn, px_kn, freqs, q16, k16);

    // 3) causal attention (128-row q-tiles, 8 warps) -> y fp16
    attn_tc<<<dim3(16, H), 256, ATN_SMEM>>>(q16, k16, v16t, y16);

    // 4) output projections (batched)
    const __half* yx16 = y16 + (size_t)S_C * D;
    {
        GJobs J; J.n = 2;
        int o = 0;
        J.j[0] = {yx16, w16 + O_P1P, p1_proj_b, x, x1x, D, D, o, 0, 0}; o += nct(L_X, D);
        J.j[1] = {y16,  w16 + O_P2P, p2_proj_b, c, x1c, D, D, o, 0, 0}; o += nct(S_C, D);
        J.j[2] = J.j[0]; J.j[3] = J.j[0];
        mma_gemm_mj<<<o, 128, MMG_SMEM>>>(J);
    }
    ln2_kernel<<<L_X + S_C, 256>>>(x1x, h16x, L_X, x1c, h16c);

    // 5) w1/w3 (one batched launch) -> fp16 outputs
    {
        GJobs J; J.n = 4;
        int o = 0;
        J.j[0] = {h16x, w16 + O_P1W1, p1_b1, nullptr, t16x1, FF, D, o, 2, 0}; o += nct(L_X, FF);
        J.j[1] = {h16x, w16 + O_P1W3, p1_b3, nullptr, t16x3, FF, D, o, 2, 0}; o += nct(L_X, FF);
        J.j[2] = {h16c, w16 + O_P2W1, p2_b1, nullptr, t16c1, FF, D, o, 2, 0}; o += nct(S_C, FF);
        J.j[3] = {h16c, w16 + O_P2W3, p2_b3, nullptr, t16c3, FF, D, o, 2, 0}; o += nct(S_C, FF);
        mma_gemm_mj<<<o, 128, MMG_SMEM>>>(J);
    }
    silu_all<<<(TT * FF / 2 + 255) / 256, 256>>>(t16x1, t16x3, g16x, L_X * FF, t16c1, t16c3, g16c, S_C * FF);

    // 6) w2 (batched)
    {
        GJobs J; J.n = 2;
        int o = 0;
        J.j[0] = {g16x, w16 + O_P1W2, p1_b2, x1x, out,                   D, FF, o, 0, 0}; o += nct(L_X, D);
        J.j[1] = {g16c, w16 + O_P2W2, p2_b2, x1c, out + (size_t)L_X * D, D, FF, o, 0, 0}; o += nct(S_C, D);
        J.j[2] = J.j[0]; J.j[3] = J.j[0];
        mma_gemm_mj<<<o, 128, MMG_SMEM>>>(J);
    }
}

// round 17
// speedup vs baseline: 1.1757x; 1.0108x over previous
#include <cuda_runtime.h>
#include <cuda_fp16.h>
#include <cstdint>
#include <math.h>

// ---------------- problem constants ----------------
#define L_X   1536
#define S_C   512
#define TT    2048          // L_X + S_C
#define D     1024
#define H     16
#define HD    64
#define FF    4096

// ---------------- scratch (device globals; no cudaMalloc allowed) ----------
__device__ float g_x1x[L_X * D];
__device__ float g_x1c[S_C * D];

// attention split-K partials (bxr 8..15 only)
__device__ float g_opart[2 * 16 * 8 * 128 * 64];
__device__ float g_mpart[2 * 16 * 8 * 128];
__device__ float g_lpart[2 * 16 * 8 * 128];

// fp16 buffers
__device__ __half g_w16  [33554432];
__device__ __half g_qk16x[L_X * 2 * D];
__device__ __half g_qk16c[S_C * 2 * D];
__device__ __half g_cln16[S_C * D];
__device__ __half g_xln16[L_X * D];
__device__ __half g_q16  [H * TT * HD];
__device__ __half g_k16  [H * TT * HD];
__device__ __half g_v16t [H * HD * TT];
__device__ __half g_y16  [TT * D];
__device__ __half g_h16x [L_X * D];
__device__ __half g_h16c [S_C * D];
__device__ __half g_t16x1[L_X * FF];
__device__ __half g_t16x3[L_X * FF];
__device__ __half g_t16c1[S_C * FF];
__device__ __half g_t16c3[S_C * FF];
__device__ __half g_g16x [L_X * FF];
__device__ __half g_g16c [S_C * FF];

// arena offsets (halves)
#define O_PCQK 0
#define O_PXQK 2097152
#define O_PCV  4194304
#define O_PXV  5242880
#define O_P1P  6291456
#define O_P2P  7340032
#define O_P1W1 8388608
#define O_P1W3 12582912
#define O_P2W1 16777216
#define O_P2W3 20971520
#define O_P1W2 25165824
#define O_P2W2 29360128

// ---------------- utils ----------------
__device__ __forceinline__ float warpSum(float v) {
    #pragma unroll
    for (int o = 16; o > 0; o >>= 1) v += __shfl_xor_sync(0xffffffffu, v, o);
    return v;
}
__device__ __forceinline__ float ex2f(float x) {
    float y;
    asm("ex2.approx.f32 %0, %1;" : "=f"(y) : "f"(x));
    return y;
}
__device__ __forceinline__ void mma_f16(float* d, const uint32_t* a, const uint32_t* b) {
    asm volatile(
        "mma.sync.aligned.m16n8k16.row.col.f32.f16.f16.f32 "
        "{%0,%1,%2,%3}, {%4,%5,%6,%7}, {%8,%9}, {%0,%1,%2,%3};"
        : "+f"(d[0]), "+f"(d[1]), "+f"(d[2]), "+f"(d[3])
        : "r"(a[0]), "r"(a[1]), "r"(a[2]), "r"(a[3]), "r"(b[0]), "r"(b[1]));
}
__device__ __forceinline__ void ldsm_x4(uint32_t* r, uint32_t addr) {
    asm volatile("ldmatrix.sync.aligned.m8n8.x4.shared.b16 {%0,%1,%2,%3}, [%4];"
        : "=r"(r[0]), "=r"(r[1]), "=r"(r[2]), "=r"(r[3]) : "r"(addr));
}
__device__ __forceinline__ uint32_t smem_u32(const void* p) {
    uint32_t a;
    asm("{ .reg .u64 t; cvta.to.shared.u64 t, %1; cvt.u32.u64 %0, t; }" : "=r"(a) : "l"(p));
    return a;
}
__device__ __forceinline__ void cp_async16(uint32_t saddr, const void* gaddr) {
    asm volatile("cp.async.cg.shared.global [%0], [%1], 16;" :: "r"(saddr), "l"(gaddr));
}
#define CP_COMMIT() asm volatile("cp.async.commit_group;" ::: "memory")
#define CP_WAIT0()  asm volatile("cp.async.wait_group 0;" ::: "memory")
#define CP_WAIT1()  asm volatile("cp.async.wait_group 1;" ::: "memory")

// ---------------- fused prologue: weight cvt (12 jobs) + LayerNorm ------
struct WJob { const float* src; __half* dst; int off; };
struct WJobs { WJob j[12]; };

#define CVT_BLKS 16384

__global__ __launch_bounds__(256)
void prologue(WJobs J,
              const float* __restrict__ lx, __half* __restrict__ lox, int rows0,
              const float* __restrict__ lc, __half* __restrict__ loc) {
    if ((int)blockIdx.x < CVT_BLKS) {
        int ji = 0;
        #pragma unroll
        for (int t = 1; t < 12; t++) if ((int)blockIdx.x >= J.j[t].off) ji = t;
        size_t idx = ((size_t)(blockIdx.x - J.j[ji].off) * 256 + threadIdx.x) * 8;
        const float4* s = (const float4*)(J.j[ji].src + idx);
        float4 v0 = s[0], v1 = s[1];
        __half2* d = (__half2*)(J.j[ji].dst + idx);
        d[0] = __floats2half2_rn(v0.x, v0.y);
        d[1] = __floats2half2_rn(v0.z, v0.w);
        d[2] = __floats2half2_rn(v1.x, v1.y);
        d[3] = __floats2half2_rn(v1.z, v1.w);
        return;
    }
    int row = blockIdx.x - CVT_BLKS;
    const float* x;
    __half* o;
    if (row < rows0) { x = lx + (size_t)row * D; o = lox + (size_t)row * D; }
    else             { x = lc + (size_t)(row - rows0) * D; o = loc + (size_t)(row - rows0) * D; }
    float4 v = *(const float4*)(x + threadIdx.x * 4);
    float s = v.x + v.y + v.z + v.w;
    float ss = v.x * v.x + v.y * v.y + v.z * v.z + v.w * v.w;
    __shared__ float shs[8], shss[8];
    float ws = warpSum(s), wss = warpSum(ss);
    int w = threadIdx.x >> 5;
    if ((threadIdx.x & 31) == 0) { shs[w] = ws; shss[w] = wss; }
    __syncthreads();
    float ts = 0.f, tss = 0.f;
    #pragma unroll
    for (int i = 0; i < 8; i++) { ts += shs[i]; tss += shss[i]; }
    float mean = ts * (1.0f / D);
    float var  = tss * (1.0f / D) - mean * mean;
    float inv  = rsqrtf(var + 1e-6f);
    __half2* o2 = (__half2*)(o + threadIdx.x * 4);
    o2[0] = __floats2half2_rn((v.x - mean) * inv, (v.y - mean) * inv);
    o2[1] = __floats2half2_rn((v.z - mean) * inv, (v.w - mean) * inv);
}

// ---------------- LayerNorm pair -> fp16 -------------------------------
__global__ __launch_bounds__(256)
void ln2_kernel(const float* __restrict__ in0, __half* __restrict__ out0,
                int rows0,
                const float* __restrict__ in1, __half* __restrict__ out1) {
    int row = blockIdx.x;
    const float* x;
    __half* o;
    if (row < rows0) { x = in0 + (size_t)row * D; o = out0 + (size_t)row * D; }
    else             { x = in1 + (size_t)(row - rows0) * D; o = out1 + (size_t)(row - rows0) * D; }
    float4 v = *(const float4*)(x + threadIdx.x * 4);
    float s = v.x + v.y + v.z + v.w;
    float ss = v.x * v.x + v.y * v.y + v.z * v.z + v.w * v.w;
    __shared__ float shs[8], shss[8];
    float ws = warpSum(s), wss = warpSum(ss);
    int w = threadIdx.x >> 5;
    if ((threadIdx.x & 31) == 0) { shs[w] = ws; shss[w] = wss; }
    __syncthreads();
    float ts = 0.f, tss = 0.f;
    #pragma unroll
    for (int i = 0; i < 8; i++) { ts += shs[i]; tss += shss[i]; }
    float mean = ts * (1.0f / D);
    float var  = tss * (1.0f / D) - mean * mean;
    float inv  = rsqrtf(var + 1e-6f);
    __half2* o2 = (__half2*)(o + threadIdx.x * 4);
    o2[0] = __floats2half2_rn((v.x - mean) * inv, (v.y - mean) * inv);
    o2[1] = __floats2half2_rn((v.z - mean) * inv, (v.w - mean) * inv);
}

// ======================================================================
// Multi-job fp16 GEMM (unchanged R12/R15 configuration).
// ======================================================================
struct GJob {
    const __half* A; const __half* B; const float* bias; const float* resid;
    void* C; int N, K, off, mode, t_off;
};
struct GJobs { GJob j[4]; int n; };

#define HST 20
#define HBUF (128 * HST)
#define MMG_SMEM (3 * 2 * HBUF * 4)

__global__ __launch_bounds__(128)
void mma_gemm_mj(GJobs jobs) {
    int ji = 0;
    if (jobs.n > 1 && (int)blockIdx.x >= jobs.j[1].off) ji = 1;
    if (jobs.n > 2 && (int)blockIdx.x >= jobs.j[2].off) ji = 2;
    if (jobs.n > 3 && (int)blockIdx.x >= jobs.j[3].off) ji = 3;
    const __half* A = jobs.j[ji].A;
    const __half* B = jobs.j[ji].B;
    const float* bias = jobs.j[ji].bias;
    const float* resid = jobs.j[ji].resid;
    void* C = jobs.j[ji].C;
    int N = jobs.j[ji].N, K = jobs.j[ji].K;
    int mode = jobs.j[ji].mode, t_off = jobs.j[ji].t_off;
    int lid0 = blockIdx.x - jobs.j[ji].off;
    int nbx = N >> 7;
    int by = lid0 / nbx, bx = lid0 - by * nbx;
    int m0 = by * 128, n0 = bx * 128;

    extern __shared__ uint32_t smw[];
    uint32_t sbase = smem_u32(smw);
    int tid = threadIdx.x;
    int wid = tid >> 5, lane = tid & 31;
    int gid = lane >> 2, tig = lane & 3;
    int warp_m = wid >> 1, warp_n = wid & 1;

    float acc[4][8][4];
    #pragma unroll
    for (int mt = 0; mt < 4; mt++)
        #pragma unroll
        for (int nt = 0; nt < 8; nt++)
            #pragma unroll
            for (int e = 0; e < 4; e++) acc[mt][nt][e] = 0.f;

    const int nchunk = K >> 5;
    int lrow = tid >> 2;
    int lblk = tid & 3;

    int tileid = lane >> 3;
    uint32_t aoff = (uint32_t)(warp_m * 64 + (tileid & 1) * 8 + (lane & 7)) * 80
                    + (uint32_t)(tileid >> 1) * 16;
    uint32_t boff = (uint32_t)(warp_n * 64 + (tileid >> 1) * 8 + (lane & 7)) * 80
                    + (uint32_t)(tileid & 1) * 16;

    #pragma unroll
    for (int pc = 0; pc < 2; pc++) {
        const __half* Ap = A + (size_t)m0 * K + pc * 32 + lblk * 8;
        const __half* Bp = B + (size_t)n0 * K + pc * 32 + lblk * 8;
        uint32_t sA = sbase + pc * 2 * HBUF * 4;
        uint32_t sB = sA + HBUF * 4;
        #pragma unroll
        for (int l = 0; l < 4; l++) {
            int r = lrow + l * 32;
            uint32_t so = (r * HST + lblk * 4) * 4;
            cp_async16(sA + so, Ap + (size_t)r * K);
            cp_async16(sB + so, Bp + (size_t)r * K);
        }
        CP_COMMIT();
    }

    int st = 0;
    for (int i = 0; i < nchunk; i++) {
        CP_WAIT1();
        __syncthreads();
        if (i + 2 < nchunk) {
            int ps = st + 2; if (ps >= 3) ps -= 3;
            const __half* Ap = A + (size_t)m0 * K + (i + 2) * 32 + lblk * 8;
            const __half* Bp = B + (size_t)n0 * K + (i + 2) * 32 + lblk * 8;
            uint32_t sA = sbase + ps * 2 * HBUF * 4;
            uint32_t sB = sA + HBUF * 4;
            #pragma unroll
            for (int l = 0; l < 4; l++) {
                int r = lrow + l * 32;
                uint32_t so = (r * HST + lblk * 4) * 4;
                cp_async16(sA + so, Ap + (size_t)r * K);
                cp_async16(sB + so, Bp + (size_t)r * K);
            }
        }
        CP_COMMIT();
        uint32_t stA = sbase + st * 2 * HBUF * 4;
        uint32_t stB = stA + HBUF * 4;
        #pragma unroll
        for (int s = 0; s < 2; s++) {
            uint32_t kbyte = s * 32;
            uint32_t af[4][4], bf[4][4];
            #pragma unroll
            for (int mt = 0; mt < 4; mt++)
                ldsm_x4(af[mt], stA + aoff + (uint32_t)mt * (16 * 80) + kbyte);
            #pragma unroll
            for (int ntp = 0; ntp < 4; ntp++)
                ldsm_x4(bf[ntp], stB + boff + (uint32_t)ntp * (16 * 80) + kbyte);
            #pragma unroll
            for (int mt = 0; mt < 4; mt++)
                #pragma unroll
                for (int ntp = 0; ntp < 4; ntp++) {
                    mma_f16(acc[mt][ntp * 2 + 0], af[mt], &bf[ntp][0]);
                    mma_f16(acc[mt][ntp * 2 + 1], af[mt], &bf[ntp][2]);
                }
        }
        st++; if (st >= 3) st = 0;
    }

    #pragma unroll
    for (int mt = 0; mt < 4; mt++) {
        #pragma unroll
        for (int nt = 0; nt < 8; nt++) {
            int row = m0 + warp_m * 64 + mt * 16 + gid;
            int col = n0 + warp_n * 64 + nt * 8 + tig * 2;
            #pragma unroll
            for (int half = 0; half < 2; half++) {
                int r = row + half * 8;
                float2 v = make_float2(acc[mt][nt][half * 2], acc[mt][nt][half * 2 + 1]);
                if (bias) {
                    float2 bv2 = *(const float2*)(bias + col);
                    v.x += bv2.x; v.y += bv2.y;
                }
                if (mode == 0) {
                    float* Cf = (float*)C;
                    size_t off = (size_t)r * N + col;
                    if (resid) {
                        float2 rv = *(const float2*)(resid + off);
                        v.x += rv.x; v.y += rv.y;
                    }
                    *(float2*)(Cf + off) = v;
                } else if (mode == 1) {
                    __half* Ch = (__half*)C;
                    int hh = col >> 6, dd = col & 63;
                    Ch[((size_t)hh * HD + dd) * TT + t_off + r]     = __float2half_rn(v.x);
                    Ch[((size_t)hh * HD + dd + 1) * TT + t_off + r] = __float2half_rn(v.y);
                } else {
                    __half* Ch = (__half*)C;
                    *(__half2*)(Ch + (size_t)r * N + col) = __floats2half2_rn(v.x, v.y);
                }
            }
        }
    }
}

// ---------------- qk finish: warp per (t,h), lane owns RoPE pair --------
__global__ __launch_bounds__(256)
void qk_finish_all(const __half* __restrict__ qkc, const __half* __restrict__ qkx,
                   const float* __restrict__ cqn, const float* __restrict__ ckn,
                   const float* __restrict__ xqn, const float* __restrict__ xkn,
                   const float* __restrict__ freqs,
                   __half* __restrict__ Q, __half* __restrict__ Ko) {
    int gidx = blockIdx.x * 8 + (threadIdx.x >> 5);
    int lane = threadIdx.x & 31;
    int t = gidx >> 4;
    int h = gidx & 15;
    const __half* qk; const float* qn; const float* kn; int row;
    if (t < S_C) { qk = qkc; qn = cqn; kn = ckn; row = t; }
    else         { qk = qkx; qn = xqn; kn = xkn; row = t - S_C; }
    size_t base = (size_t)row * (2 * D) + h * HD + lane * 2;
    float2 qv = __half22float2(*(const __half2*)(qk + base));
    float2 kv = __half22float2(*(const __half2*)(qk + base + D));
    float sq = qv.x * qv.x + qv.y * qv.y;
    float sk = kv.x * kv.x + kv.y * kv.y;
    #pragma unroll
    for (int o = 16; o > 0; o >>= 1) {
        sq += __shfl_xor_sync(0xffffffffu, sq, o);
        sk += __shfl_xor_sync(0xffffffffu, sk, o);
    }
    float rq = rsqrtf(sq * (1.0f / HD) + 1e-6f);
    float rk = rsqrtf(sk * (1.0f / HD) + 1e-6f);
    float2 qw = *(const float2*)(qn + lane * 2);
    float2 kw = *(const float2*)(kn + lane * 2);
    float q0 = qv.x * rq * qw.x, q1 = qv.y * rq * qw.y;
    float k0 = kv.x * rk * kw.x, k1 = kv.y * rk * kw.y;
    float2 f = *(const float2*)(freqs + ((size_t)t * 32 + lane) * 2);
    float cs = f.x, sn = f.y;
    const float QSC = 0.125f * 1.4426950408889634f;
    float oq0 = (q0 * cs - q1 * sn) * QSC;
    float oq1 = (q0 * sn + q1 * cs) * QSC;
    float ok0 = k0 * cs - k1 * sn;
    float ok1 = k0 * sn + k1 * cs;
    size_t off = ((size_t)h * TT + t) * HD + lane * 2;
    *(__half2*)(Q + off)  = __floats2half2_rn(oq0, oq1);
    *(__half2*)(Ko + off) = __floats2half2_rn(ok0, ok1);
}

// ======================================================================
// fp16 flash attention, 128-row q-tiles, 8 warps, split-K for heavy tiles.
// Grid (24, H): ids 0..15 = split halves of bxr 15..8; 16..23 = bxr 7..0.
// Split CTAs write unnormalized fp32 partials + (m,l); combine merges.
// ======================================================================
#define AHS 72
#define AWS 36
#define ATN_SMEM (512 * AWS * 4)

__global__ __launch_bounds__(256)
void attn_tc(const __half* __restrict__ Q, const __half* __restrict__ K,
             const __half* __restrict__ V, __half* __restrict__ Y,
             float* __restrict__ Opart, float* __restrict__ Mpart,
             float* __restrict__ Lpart) {
    extern __shared__ uint32_t smw[];
    uint32_t sbase = smem_u32(smw);
    int tid = threadIdx.x, wid = tid >> 5, lane = tid & 31;
    int gid = lane >> 2, tig = lane & 3;
    int id = blockIdx.x;
    int h = blockIdx.y;
    int bxr, part, kt0, kt1, splitf;
    if (id < 16) {
        splitf = 1;
        bxr = 15 - (id >> 1);
        part = id & 1;
        int ntile = 2 * bxr + 2, halfn = ntile >> 1;
        kt0 = part ? halfn : 0;
        kt1 = part ? ntile : halfn;
    } else {
        splitf = 0; part = 0;
        bxr = 7 - (id - 16);
        kt0 = 0; kt1 = 2 * bxr + 2;
    }
    int q0 = bxr * 128;
    int mask_from = 2 * bxr;               // last two global k-tiles
    const __half* Qh = Q + (size_t)h * TT * HD;
    const __half* Kh = K + (size_t)h * TT * HD;
    const __half* Vh = V + (size_t)h * HD * TT;

    const uint32_t* QsW = smw;
    uint32_t* PwW = smw + 384 * AWS;

    int lrowq = tid >> 1;
    int lblkq = tid & 1;
    int lrowk = tid >> 2;
    int lblkk = tid & 3;

    int tileid = lane >> 3;
    uint32_t poff = (uint32_t)(wid * 16 + (tileid & 1) * 8 + (lane & 7)) * (AHS * 2)
                    + (uint32_t)(tileid >> 1) * 16;
    uint32_t boff = (uint32_t)((tileid >> 1) * 8 + (lane & 7)) * (AHS * 2)
                    + (uint32_t)(tileid & 1) * 16;

    // prologue: Q tile + K/V tile kt0
    {
        uint32_t qb = sbase;
        uint32_t kb = sbase + (128 * AWS) * 4;
        uint32_t vb = sbase + (256 * AWS) * 4;
        const __half* Kp = Kh + (size_t)kt0 * 64 * HD;
        const __half* Vp = Vh + kt0 * 64;
        #pragma unroll
        for (int j = 0; j < 4; j++) {
            uint32_t so = (lrowq * AHS + lblkq * 32 + j * 8) * 2;
            cp_async16(qb + so, Qh + (size_t)(q0 + lrowq) * HD + lblkq * 32 + j * 8);
        }
        #pragma unroll
        for (int j = 0; j < 2; j++) {
            uint32_t so = (lrowk * AHS + lblkk * 8 + j * 32) * 2;
            cp_async16(kb + so, Kp + (size_t)lrowk * HD + lblkk * 8 + j * 32);
            cp_async16(vb + so, Vp + (size_t)lrowk * TT + lblkk * 8 + j * 32);
        }
        CP_COMMIT();
    }
    CP_WAIT0();
    __syncthreads();

    uint32_t qf[4][4];
    int qrow = wid * 16 + gid;
    #pragma unroll
    for (int ks = 0; ks < 4; ks++) {
        qf[ks][0] = QsW[qrow * AWS + ks * 8 + tig];
        qf[ks][1] = QsW[(qrow + 8) * AWS + ks * 8 + tig];
        qf[ks][2] = QsW[qrow * AWS + ks * 8 + tig + 4];
        qf[ks][3] = QsW[(qrow + 8) * AWS + ks * 8 + tig + 4];
    }
    __syncwarp();

    float ofr[8][4];
    #pragma unroll
    for (int ot = 0; ot < 8; ot++)
        #pragma unroll
        for (int e = 0; e < 4; e++) ofr[ot][e] = 0.f;
    float m0r = -INFINITY, m1r = -INFINITY, l0r = 0.f, l1r = 0.f;

    for (int kt = kt0; kt < kt1; kt++) {
        int li = kt - kt0;
        int k0g = kt * 64;
        int buf = li & 1;
        uint32_t kbase = sbase + ((128 + buf * 64) * AWS) * 4;
        uint32_t vbase = sbase + ((256 + buf * 64) * AWS) * 4;
        uint32_t pbase = sbase + (384 * AWS) * 4;
        if (li > 0) { CP_WAIT0(); __syncthreads(); }
        float sacc[8][4];
        #pragma unroll
        for (int nt = 0; nt < 8; nt++)
            #pragma unroll
            for (int e = 0; e < 4; e++) sacc[nt][e] = 0.f;
        #pragma unroll
        for (int ks = 0; ks < 4; ks++) {
            uint32_t bk[4][4];
            #pragma unroll
            for (int kp = 0; kp < 4; kp++)
                ldsm_x4(bk[kp], kbase + boff + (uint32_t)kp * (16 * AHS * 2) + ks * 32);
            #pragma unroll
            for (int kp = 0; kp < 4; kp++) {
                mma_f16(sacc[kp * 2 + 0], qf[ks], &bk[kp][0]);
                mma_f16(sacc[kp * 2 + 1], qf[ks], &bk[kp][2]);
            }
        }
        if (kt + 1 < kt1) {
            uint32_t kb = sbase + ((128 + (buf ^ 1) * 64) * AWS) * 4;
            uint32_t vb = sbase + ((256 + (buf ^ 1) * 64) * AWS) * 4;
            const __half* Kp = Kh + (size_t)(k0g + 64) * HD;
            const __half* Vp = Vh + k0g + 64;
            #pragma unroll
            for (int j = 0; j < 2; j++) {
                uint32_t so = (lrowk * AHS + lblkk * 8 + j * 32) * 2;
                cp_async16(kb + so, Kp + (size_t)lrowk * HD + lblkk * 8 + j * 32);
                cp_async16(vb + so, Vp + (size_t)lrowk * TT + lblkk * 8 + j * 32);
            }
        }
        CP_COMMIT();
        if (kt >= mask_from) {
            int r0 = q0 + wid * 16 + gid;
            #pragma unroll
            for (int nt = 0; nt < 8; nt++) {
                int c0 = k0g + nt * 8 + tig * 2;
                if (c0 > r0)     sacc[nt][0] = -INFINITY;
                if (c0 + 1 > r0) sacc[nt][1] = -INFINITY;
                if (c0 > r0 + 8)     sacc[nt][2] = -INFINITY;
                if (c0 + 1 > r0 + 8) sacc[nt][3] = -INFINITY;
            }
        }
        float tm0 = -INFINITY, tm1 = -INFINITY;
        #pragma unroll
        for (int nt = 0; nt < 8; nt++) {
            tm0 = fmaxf(tm0, fmaxf(sacc[nt][0], sacc[nt][1]));
            tm1 = fmaxf(tm1, fmaxf(sacc[nt][2], sacc[nt][3]));
        }
        #pragma unroll
        for (int o = 1; o < 4; o <<= 1) {
            tm0 = fmaxf(tm0, __shfl_xor_sync(0xffffffffu, tm0, o));
            tm1 = fmaxf(tm1, __shfl_xor_sync(0xffffffffu, tm1, o));
        }
        float nm0 = fmaxf(m0r, tm0), nm1 = fmaxf(m1r, tm1);
        float c0 = ex2f(m0r - nm0), c1 = ex2f(m1r - nm1);
        m0r = nm0; m1r = nm1;
        float ps0 = 0.f, ps1 = 0.f;
        int row0 = wid * 16 + gid, row1 = row0 + 8;
        #pragma unroll
        for (int nt = 0; nt < 8; nt++) {
            float p00 = ex2f(sacc[nt][0] - nm0);
            float p01 = ex2f(sacc[nt][1] - nm0);
            float p10 = ex2f(sacc[nt][2] - nm1);
            float p11 = ex2f(sacc[nt][3] - nm1);
            ps0 += p00 + p01; ps1 += p10 + p11;
            __half2 h0 = __floats2half2_rn(p00, p01);
            __half2 h1 = __floats2half2_rn(p10, p11);
            PwW[row0 * AWS + nt * 4 + tig] = *(uint32_t*)&h0;
            PwW[row1 * AWS + nt * 4 + tig] = *(uint32_t*)&h1;
        }
        #pragma unroll
        for (int o = 1; o < 4; o <<= 1) {
            ps0 += __shfl_xor_sync(0xffffffffu, ps0, o);
            ps1 += __shfl_xor_sync(0xffffffffu, ps1, o);
        }
        l0r = l0r * c0 + ps0;
        l1r = l1r * c1 + ps1;
        #pragma unroll
        for (int ot = 0; ot < 8; ot++) {
            ofr[ot][0] *= c0; ofr[ot][1] *= c0;
            ofr[ot][2] *= c1; ofr[ot][3] *= c1;
        }
        __syncwarp();
        #pragma unroll
        for (int ks = 0; ks < 4; ks++) {
            uint32_t af[4];
            ldsm_x4(af, pbase + poff + ks * 32);
            uint32_t bv[4][4];
            #pragma unroll
            for (int vp = 0; vp < 4; vp++)
                ldsm_x4(bv[vp], vbase + boff + (uint32_t)vp * (16 * AHS * 2) + ks * 32);
            #pragma unroll
            for (int vp = 0; vp < 4; vp++) {
                mma_f16(ofr[vp * 2 + 0], af, &bv[vp][0]);
                mma_f16(ofr[vp * 2 + 1], af, &bv[vp][2]);
            }
        }
        __syncwarp();
    }
    int row0 = wid * 16 + gid, row1 = row0 + 8;
    if (!splitf) {
        float i0 = 1.0f / l0r, i1 = 1.0f / l1r;
        int t0 = q0 + row0, t1 = q0 + row1;
        #pragma unroll
        for (int ot = 0; ot < 8; ot++) {
            int col = h * HD + ot * 8 + tig * 2;
            *(__half2*)(Y + (size_t)t0 * D + col) = __floats2half2_rn(ofr[ot][0] * i0, ofr[ot][1] * i0);
            *(__half2*)(Y + (size_t)t1 * D + col) = __floats2half2_rn(ofr[ot][2] * i1, ofr[ot][3] * i1);
        }
    } else {
        int sq = bxr - 8;
        size_t rb = (((size_t)part * 16 + h) * 8 + sq) * 128;
        float* O0 = Opart + (rb + row0) * 64;
        float* O1 = Opart + (rb + row1) * 64;
        #pragma unroll
        for (int ot = 0; ot < 8; ot++) {
            int col = ot * 8 + tig * 2;
            *(float2*)(O0 + col) = make_float2(ofr[ot][0], ofr[ot][1]);
            *(float2*)(O1 + col) = make_float2(ofr[ot][2], ofr[ot][3]);
        }
        if (tig == 0) {
            Mpart[rb + row0] = m0r; Lpart[rb + row0] = l0r;
            Mpart[rb + row1] = m1r; Lpart[rb + row1] = l1r;
        }
    }
}

// ---------------- split-K combine -> Y ----------------------------------
__global__ __launch_bounds__(64)
void attn_combine(const float* __restrict__ Opart, const float* __restrict__ Mpart,
                  const float* __restrict__ Lpart, __half* __restrict__ Y) {
    int rowid = blockIdx.x;               // (h*8+sq)*128 + row
    int d = threadIdx.x;                  // 0..63
    int row = rowid & 127;
    int hs = rowid >> 7;
    int sq = hs & 7;
    int h = hs >> 3;
    size_t i0 = (((size_t)0 * 16 + h) * 8 + sq) * 128 + row;
    size_t i1 = (((size_t)1 * 16 + h) * 8 + sq) * 128 + row;
    float m0 = Mpart[i0], m1 = Mpart[i1];
    float l0 = Lpart[i0], l1 = Lpart[i1];
    float m = fmaxf(m0, m1);
    float s0 = ex2f(m0 - m), s1 = ex2f(m1 - m);
    float inv = 1.0f / (l0 * s0 + l1 * s1);
    float o = (Opart[i0 * 64 + d] * s0 + Opart[i1 * 64 + d] * s1) * inv;
    int t = (sq + 8) * 128 + row;
    Y[(size_t)t * D + h * HD + d] = __float2half_rn(o);
}

// ---------------- SiLU gate fp16 -> fp16 --------------------------------
__global__ __launch_bounds__(256)
void silu_all(const __half* __restrict__ a0, const __half* __restrict__ b0,
              __half* __restrict__ g0, int n0,
              const __half* __restrict__ a1, const __half* __restrict__ b1,
              __half* __restrict__ g1, int n1) {
    const float L2E = 1.4426950408889634f;
    int i = blockIdx.x * 256 + threadIdx.x;
    int h0 = n0 >> 1;
    if (i < h0) {
        __half2 av = ((const __half2*)a0)[i];
        __half2 bv = ((const __half2*)b0)[i];
        float x0 = __half2float(__low2half(av)), x1 = __half2float(__high2half(av));
        float s0 = x0 / (1.0f + ex2f(-x0 * L2E)) * __half2float(__low2half(bv));
        float s1 = x1 / (1.0f + ex2f(-x1 * L2E)) * __half2float(__high2half(bv));
        ((__half2*)g0)[i] = __floats2half2_rn(s0, s1);
    } else if (i < h0 + (n1 >> 1)) {
        int j = i - h0;
        __half2 av = ((const __half2*)a1)[j];
        __half2 bv = ((const __half2*)b1)[j];
        float x0 = __half2float(__low2half(av)), x1 = __half2float(__high2half(av));
        float s0 = x0 / (1.0f + ex2f(-x0 * L2E)) * __half2float(__low2half(bv));
        float s1 = x1 / (1.0f + ex2f(-x1 * L2E)) * __half2float(__high2half(bv));
        ((__half2*)g1)[j] = __floats2half2_rn(s0, s1);
    }
}

// ---------------- host launcher ----------------
static inline int nct(int M, int N) { return (M / 128) * (N / 128); }

extern "C" void kernel_launch(void* const* d_in, const int* in_sizes, int n_in,
                              void* d_out, int out_size) {
    const float* x        = (const float*)d_in[0];
    const float* c        = (const float*)d_in[1];
    const float* freqs    = (const float*)d_in[2];
    const float* px_qk_w  = (const float*)d_in[3];
    const float* px_qn    = (const float*)d_in[4];
    const float* px_kn    = (const float*)d_in[5];
    const float* px_v_w   = (const float*)d_in[6];
    const float* px_v_b   = (const float*)d_in[7];
    const float* pc_qk_w  = (const float*)d_in[8];
    const float* pc_qn    = (const float*)d_in[9];
    const float* pc_kn    = (const float*)d_in[10];
    const float* pc_v_w   = (const float*)d_in[11];
    const float* pc_v_b   = (const float*)d_in[12];
    const float* p1_proj_w = (const float*)d_in[13];
    const float* p1_proj_b = (const float*)d_in[14];
    const float* p1_w1    = (const float*)d_in[15];
    const float* p1_b1    = (const float*)d_in[16];
    const float* p1_w3    = (const float*)d_in[17];
    const float* p1_b3    = (const float*)d_in[18];
    const float* p1_w2    = (const float*)d_in[19];
    const float* p1_b2    = (const float*)d_in[20];
    const float* p2_proj_w = (const float*)d_in[21];
    const float* p2_proj_b = (const float*)d_in[22];
    const float* p2_w1    = (const float*)d_in[23];
    const float* p2_b1    = (const float*)d_in[24];
    const float* p2_w3    = (const float*)d_in[25];
    const float* p2_b3    = (const float*)d_in[26];
    const float* p2_w2    = (const float*)d_in[27];
    const float* p2_b2    = (const float*)d_in[28];
    float* out = (float*)d_out;

    float *x1x, *x1c, *opart, *mpart, *lpart;
    __half *w16, *qk16x, *qk16c, *cln16, *xln16, *q16, *k16, *v16t, *y16;
    __half *h16x, *h16c, *t16x1, *t16x3, *t16c1, *t16c3, *g16x, *g16c;
    cudaGetSymbolAddress((void**)&x1x, g_x1x);
    cudaGetSymbolAddress((void**)&x1c, g_x1c);
    cudaGetSymbolAddress((void**)&opart, g_opart);
    cudaGetSymbolAddress((void**)&mpart, g_mpart);
    cudaGetSymbolAddress((void**)&lpart, g_lpart);
    cudaGetSymbolAddress((void**)&w16,   g_w16);
    cudaGetSymbolAddress((void**)&qk16x, g_qk16x);
    cudaGetSymbolAddress((void**)&qk16c, g_qk16c);
    cudaGetSymbolAddress((void**)&cln16, g_cln16);
    cudaGetSymbolAddress((void**)&xln16, g_xln16);
    cudaGetSymbolAddress((void**)&q16,   g_q16);
    cudaGetSymbolAddress((void**)&k16,   g_k16);
    cudaGetSymbolAddress((void**)&v16t,  g_v16t);
    cudaGetSymbolAddress((void**)&y16,   g_y16);
    cudaGetSymbolAddress((void**)&h16x,  g_h16x);
    cudaGetSymbolAddress((void**)&h16c,  g_h16c);
    cudaGetSymbolAddress((void**)&t16x1, g_t16x1);
    cudaGetSymbolAddress((void**)&t16x3, g_t16x3);
    cudaGetSymbolAddress((void**)&t16c1, g_t16c1);
    cudaGetSymbolAddress((void**)&t16c3, g_t16c3);
    cudaGetSymbolAddress((void**)&g16x,  g_g16x);
    cudaGetSymbolAddress((void**)&g16c,  g_g16c);

    cudaFuncSetAttribute(attn_tc, cudaFuncAttributeMaxDynamicSharedMemorySize, ATN_SMEM);
    cudaFuncSetAttribute(mma_gemm_mj, cudaFuncAttributeMaxDynamicSharedMemorySize, MMG_SMEM);

    // 0) fused prologue: weight cvt + LayerNorm both streams
    {
        WJobs W;
        int o = 0;
        W.j[0]  = {pc_qk_w,  w16 + O_PCQK, o}; o += 1024;
        W.j[1]  = {px_qk_w,  w16 + O_PXQK, o}; o += 1024;
        W.j[2]  = {pc_v_w,   w16 + O_PCV,  o}; o += 512;
        W.j[3]  = {px_v_w,   w16 + O_PXV,  o}; o += 512;
        W.j[4]  = {p1_proj_w, w16 + O_P1P, o}; o += 512;
        W.j[5]  = {p2_proj_w, w16 + O_P2P, o}; o += 512;
        W.j[6]  = {p1_w1,    w16 + O_P1W1, o}; o += 2048;
        W.j[7]  = {p1_w3,    w16 + O_P1W3, o}; o += 2048;
        W.j[8]  = {p2_w1,    w16 + O_P2W1, o}; o += 2048;
        W.j[9]  = {p2_w3,    w16 + O_P2W3, o}; o += 2048;
        W.j[10] = {p1_w2,    w16 + O_P1W2, o}; o += 2048;
        W.j[11] = {p2_w2,    w16 + O_P2W2, o}; o += 2048;
        prologue<<<CVT_BLKS + L_X + S_C, 256>>>(W, x, xln16, L_X, c, cln16);
    }

    // 2) QKV GEMMs
    {
        GJobs J; J.n = 4;
        int o = 0;
        J.j[0] = {cln16, w16 + O_PCQK, nullptr, nullptr, qk16c, 2 * D, D, o, 2, 0};  o += nct(S_C, 2 * D);
        J.j[1] = {cln16, w16 + O_PCV,  pc_v_b,  nullptr, v16t,  D,     D, o, 1, 0};  o += nct(S_C, D);
        J.j[2] = {xln16, w16 + O_PXQK, nullptr, nullptr, qk16x, 2 * D, D, o, 2, 0};  o += nct(L_X, 2 * D);
        J.j[3] = {xln16, w16 + O_PXV,  px_v_b,  nullptr, v16t,  D,     D, o, 1, S_C}; o += nct(L_X, D);
        mma_gemm_mj<<<o, 128, MMG_SMEM>>>(J);
    }
    qk_finish_all<<<TT * H / 8, 256>>>(qk16c, qk16x, pc_qn, pc_kn, px_qn, px_kn, freqs, q16, k16);

    // 3) causal attention (split-K) -> y fp16 (+ combine for split tiles)
    attn_tc<<<dim3(24, H), 256, ATN_SMEM>>>(q16, k16, v16t, y16, opart, mpart, lpart);
    attn_combine<<<16 * 8 * 128, 64>>>(opart, mpart, lpart, y16);

    // 4) output projections (batched)
    const __half* yx16 = y16 + (size_t)S_C * D;
    {
        GJobs J; J.n = 2;
        int o = 0;
        J.j[0] = {yx16, w16 + O_P1P, p1_proj_b, x, x1x, D, D, o, 0, 0}; o += nct(L_X, D);
        J.j[1] = {y16,  w16 + O_P2P, p2_proj_b, c, x1c, D, D, o, 0, 0}; o += nct(S_C, D);
        J.j[2] = J.j[0]; J.j[3] = J.j[0];
        mma_gemm_mj<<<o, 128, MMG_SMEM>>>(J);
    }
    ln2_kernel<<<L_X + S_C, 256>>>(x1x, h16x, L_X, x1c, h16c);

    // 5) w1/w3 (one batched launch) -> fp16 outputs
    {
        GJobs J; J.n = 4;
        int o = 0;
        J.j[0] = {h16x, w16 + O_P1W1, p1_b1, nullptr, t16x1, FF, D, o, 2, 0}; o += nct(L_X, FF);
        J.j[1] = {h16x, w16 + O_P1W3, p1_b3, nullptr, t16x3, FF, D, o, 2, 0}; o += nct(L_X, FF);
        J.j[2] = {h16c, w16 + O_P2W1, p2_b1, nullptr, t16c1, FF, D, o, 2, 0}; o += nct(S_C, FF);
        J.j[3] = {h16c, w16 + O_P2W3, p2_b3, nullptr, t16c3, FF, D, o, 2, 0}; o += nct(S_C, FF);
        mma_gemm_mj<<<o, 128, MMG_SMEM>>>(J);
    }
    silu_all<<<(TT * FF / 2 + 255) / 256, 256>>>(t16x1, t16x3, g16x, L_X * FF, t16c1, t16c3, g16c, S_C * FF);

    // 6) w2 (batched)
    {
        GJobs J; J.n = 2;
        int o = 0;
        J.j[0] = {g16x, w16 + O_P1W2, p1_b2, x1x, out,                   D, FF, o, 0, 0}; o += nct(L_X, D);
        J.j[1] = {g16c, w16 + O_P2W2, p2_b2, x1c, out + (size_t)L_X * D, D, FF, o, 0, 0}; o += nct(S_C, D);
        J.j[2] = J.j[0]; J.j[3] = J.j[0];
        mma_gemm_mj<<<o, 128, MMG_SMEM>>>(J);
    }
}